// round 8
// baseline (speedup 1.0000x reference)
#include <cuda_runtime.h>
#include <cstdint>

typedef unsigned long long ull;

#define NB 32
#define NA 8400
#define NC 80
#define KTOP 1024
#define NG 32
#define NSUP 16
#define MAX_DET 300
#define CONF_NMS 0.25f
#define IOU_NMS 0.45f
#define CONF_MATCH 0.5f
#define IOU_MATCH 0.6f
#define MAX_WH 7680.0f

// histogram select parameters: bucket = 1 + ((fb - 0x3E800000) >> 11), monotone in conf
#define FB_BASE 0x3E800000u
#define BSHIFT 11
#define NBPAD 9216          // 1024 threads * CH chunks, covers 8193 buckets
#define CH 9
#define CAP 2048            // gather capacity / sort size (expected ~1100)

// ---------------- scratch (global __device__ arrays; no allocation) ----------------
__device__ unsigned               g_hist[NB * NBPAD];   // zero-init; k_select re-zeroes
__device__ __align__(16) float    g_conf[NB * NA];
__device__ __align__(16) int      g_cls[NB * NA];
__device__ float4                 g_box4[NB * KTOP];    // unshifted x1y1x2y2
__device__ float4                 g_sbox4[NB * KTOP];   // class-shifted
__device__ float                  g_area[NB * KTOP];    // area of shifted box
__device__ float                  g_conf_k[NB * KTOP];
__device__ int                    g_cls_k[NB * KTOP];
__device__ __align__(16) ull      g_mask[NB * KTOP * 16];

// upper-triangle 128x128 tile pairs (tr <= tc) over 8 tiles
__device__ const unsigned char c_tr[36] =
    {0,0,0,0,0,0,0,0, 1,1,1,1,1,1,1, 2,2,2,2,2,2, 3,3,3,3,3, 4,4,4,4, 5,5,5, 6,6, 7};
__device__ const unsigned char c_tc[36] =
    {0,1,2,3,4,5,6,7, 1,2,3,4,5,6,7, 2,3,4,5,6,7, 3,4,5,6,7, 4,5,6,7, 5,6,7, 6,7, 7};

__device__ __forceinline__ int conf_bucket(float c) {
    if (c <= 0.0f) return 0;
    unsigned fb = __float_as_uint(c);
    return 1 + (int)((fb - FB_BASE) >> BSHIFT);
}

// ---------------- Kernel 1: decode conf/cls (scalar, high occupancy) + histogram ---
__global__ void k_decode(const float* __restrict__ preds) {
    int t = blockIdx.x * 256 + threadIdx.x;        // grid exact: 1050*256 == NB*NA
    int b = t / NA;
    int a = t - b * NA;
    const float* sc = preds + ((size_t)b * 84 + 4) * NA + a;
    float m = sc[0];
    int arg = 0;
#pragma unroll 8
    for (int c = 1; c < NC; c++) {
        float v = sc[(size_t)c * NA];
        if (v > m) { m = v; arg = c; }             // strict > keeps FIRST max
    }
    m = (m > CONF_NMS) ? m : 0.0f;
    g_conf[t] = m;
    g_cls[t]  = arg;

    // warp-aggregated histogram update (bucket 0 takes ~1/3 of all traffic)
    int bk = conf_bucket(m);
    int key = (bk == 0) ? b : (0x10000 + t);       // group zero-bucket lanes per batch
    unsigned peers = __match_any_sync(0xFFFFFFFFu, key);
    if ((threadIdx.x & 31) == (__ffs(peers) - 1))
        atomicAdd(&g_hist[b * NBPAD + bk], (unsigned)__popc(peers));
}

// ---------------- Kernel 2: histogram select + bitonic sort of <=2048 candidates ---
// keys = (~float_bits(conf) << 32) | index : ascending sort == conf desc, idx asc
// (identical ordering to lax.top_k incl. ties)
__global__ __launch_bounds__(1024, 1) void k_select(const float* __restrict__ preds) {
    extern __shared__ ull skey[];               // CAP entries
    __shared__ unsigned s_suf[1024];
    __shared__ int s_bstar;
    __shared__ int s_cnt;

    const int b = blockIdx.x;
    const int tid = threadIdx.x;
    const int q0 = tid * CH;

    // chunk sums
    unsigned v = 0;
#pragma unroll
    for (int k = 0; k < CH; k++) v += g_hist[b * NBPAD + q0 + k];
    s_suf[tid] = v;
    __syncthreads();
    // inclusive suffix scan (Hillis-Steele)
    for (int d = 1; d < 1024; d <<= 1) {
        unsigned add = (tid + d < 1024) ? s_suf[tid + d] : 0u;
        __syncthreads();
        v += add;
        s_suf[tid] = v;
        __syncthreads();
    }
    // unique crossing thread finds threshold bucket B*: largest bucket with
    // count(buckets >= B*) >= KTOP
    unsigned nxt = (tid < 1023) ? s_suf[tid + 1] : 0u;
    if (s_suf[tid] >= KTOP && !(tid < 1023 && nxt >= KTOP)) {
        unsigned running = nxt;
        int B = q0;
        for (int q = q0 + CH - 1; q >= q0; q--) {
            running += g_hist[b * NBPAD + q];
            if (running >= KTOP) { B = q; break; }
        }
        s_bstar = B;
    }
    if (tid == 0) s_cnt = 0;
    for (int i = tid; i < CAP; i += 1024) skey[i] = ~0ULL;   // padding sorts last
    __syncthreads();

    // hist fully consumed -> re-zero for the next graph replay (replaces k_zero)
    for (int i = tid; i < NBPAD; i += 1024) g_hist[b * NBPAD + i] = 0u;

    const int Bs = s_bstar;
    for (int i = tid; i < NA; i += 1024) {
        float c = g_conf[b * NA + i];
        if (conf_bucket(c) >= Bs) {
            int p = atomicAdd(&s_cnt, 1);
            if (p < CAP)
                skey[p] = ((ull)(~__float_as_uint(c)) << 32) | (unsigned)i;
        }
    }
    __syncthreads();

    // bitonic sort of CAP keys
    for (unsigned k = 2; k <= CAP; k <<= 1) {
        for (unsigned j = k >> 1; j > 0; j >>= 1) {
#pragma unroll 1
            for (unsigned i = tid; i < CAP; i += 1024) {
                unsigned ixj = i ^ j;
                if (ixj > i) {
                    ull x = skey[i];
                    ull y = skey[ixj];
                    bool up = ((i & k) == 0);
                    if (up ? (x > y) : (x < y)) { skey[i] = y; skey[ixj] = x; }
                }
            }
            __syncthreads();
        }
    }

    // emit top-KTOP (guaranteed >= KTOP gathered)
    ull key = skey[tid];
    unsigned fb = ~(unsigned)(key >> 32);
    float conf = __uint_as_float(fb);
    int a = (int)(key & 0xFFFFFFFFu);
    const float* base = preds + (size_t)b * 84 * NA;
    float cx = base[a];
    float cy = base[NA + a];
    float w  = base[2 * NA + a];
    float h  = base[3 * NA + a];
    float x1 = cx - w * 0.5f, y1 = cy - h * 0.5f;
    float x2 = cx + w * 0.5f, y2 = cy + h * 0.5f;
    int o = b * KTOP + tid;
    int cls = g_cls[b * NA + a];
    float sh = (float)cls * MAX_WH;
    float sx1 = x1 + sh, sy1 = y1 + sh, sx2 = x2 + sh, sy2 = y2 + sh;
    g_box4[o]  = make_float4(x1, y1, x2, y2);
    g_sbox4[o] = make_float4(sx1, sy1, sx2, sy2);
    g_area[o]  = (sx2 - sx1) * (sy2 - sy1);     // area AFTER shift (bit-matches ref)
    g_conf_k[o] = conf;
    g_cls_k[o]  = cls;
}

// ---------------- Kernel 3: NMS IoU bit-mask, upper triangle only, ballot-based ----
// grid (36, NB): block = one 128x128 tile (tr<=tc). 256 threads, 8 warps.
// warp w, iter rr: row_local = rr*8+w. Lanes = 32 cols; cc in [0,4) col-chunks.
// mask word built by __ballot_sync -> zero shift/OR ALU.
__global__ __launch_bounds__(256) void k_nmsmask() {
    __shared__ float4 srow[128];
    __shared__ float  sarea[128];
    const int b = blockIdx.y;
    const int tr = c_tr[blockIdx.x];
    const int tc = c_tc[blockIdx.x];
    const int tid = threadIdx.x;
    const int lane = tid & 31;
    const int w = tid >> 5;

    if (tid < 128) {
        srow[tid]  = g_sbox4[b * KTOP + tr * 128 + tid];
        sarea[tid] = g_area[b * KTOP + tr * 128 + tid];
    }
    // column boxes in registers (4 per lane)
    float4 cb[4];
    float  ca[4];
#pragma unroll
    for (int cc = 0; cc < 4; cc++) {
        int j = tc * 128 + cc * 32 + lane;
        cb[cc] = g_sbox4[b * KTOP + j];
        ca[cc] = g_area[b * KTOP + j];
    }
    __syncthreads();

    const bool diag = (tr == tc);
#pragma unroll 4
    for (int rr = 0; rr < 16; rr++) {
        int rl = rr * 8 + w;
        int row = tr * 128 + rl;
        float4 bi = srow[rl];
        float  ai = sarea[rl];
        unsigned bl[4] = {0u, 0u, 0u, 0u};
        bool skip_lo = diag && (rr >= 8);    // rows >= 64 of diag tile: word 2*tc dead
#pragma unroll
        for (int cc = 0; cc < 4; cc++) {
            if (skip_lo && cc < 2) continue;              // warp-uniform skip
            float4 bj = cb[cc];
            float lx = fmaxf(bi.x, bj.x);
            float ly = fmaxf(bi.y, bj.y);
            float rx = fminf(bi.z, bj.z);
            float ry = fminf(bi.w, bj.w);
            float iw = fmaxf(rx - lx, 0.0f);
            float ih = fmaxf(ry - ly, 0.0f);
            float inter = iw * ih;
            float iou = inter / (ai + ca[cc] - inter + 1e-9f);   // same arithmetic
            bl[cc] = __ballot_sync(0xFFFFFFFFu, iou > IOU_NMS);
        }
        ull* mrow = &g_mask[((size_t)b * KTOP + row) * 16];
        if (!skip_lo) {
            if (lane == 0) mrow[2 * tc]     = (ull)bl[0] | ((ull)bl[1] << 32);
            if (lane == 1) mrow[2 * tc + 1] = (ull)bl[2] | ((ull)bl[3] << 32);
        } else {
            if (lane == 1) mrow[2 * tc + 1] = (ull)bl[2] | ((ull)bl[3] << 32);
        }
    }
}

// ---------------- Kernel 4: grouped NMS resolve (triangular) + GT match (fused) ----
__global__ __launch_bounds__(1024, 1) void k_resolve_match(
        const float* __restrict__ gt_boxes,
        const int* __restrict__ gt_cls,
        const void* __restrict__ gt_mask_raw,
        const int* __restrict__ cat_to_super,
        float* __restrict__ out) {
    extern __shared__ char dyn[];
    ull* smask = (ull*)dyn;                   // KTOP*16 u64 = 128 KB

    __shared__ float4 sbox[KTOP];
    __shared__ float  sconf[KTOP];
    __shared__ int    scls[KTOP];
    __shared__ unsigned char sval[KTOP];
    __shared__ unsigned char spv[KTOP];
    __shared__ ull    s_k64[16];
    __shared__ int    s_base[17];
    __shared__ float  s_biou[NG];
    __shared__ float  s_bconf[NG];
    __shared__ int    s_hit[NG];
    __shared__ int    s_gm[NG];
    __shared__ float  cat_counts[NC];
    __shared__ float  sup_counts[NSUP];
    __shared__ int    s_npred;
    __shared__ int    s_is_u8;

    const int b = blockIdx.x;
    const int tid = threadIdx.x;
    const int o = b * KTOP + tid;

    // bulk copy mask batch-slice into smem (coalesced; lower-triangle words are
    // garbage but never read)
    const float4* msrc = (const float4*)(g_mask + (size_t)b * KTOP * 16);
    float4* mdst = (float4*)smask;
#pragma unroll
    for (int i = 0; i < 8; i++) mdst[tid + i * 1024] = msrc[tid + i * 1024];

    float cf = g_conf_k[o];
    sbox[tid]  = g_box4[o];
    sconf[tid] = cf;
    scls[tid]  = g_cls_k[o];
    sval[tid]  = (cf > 0.0f) ? 1 : 0;
    if (tid == 0) { s_npred = 0; s_is_u8 = 0; }
    if (tid < NC)   cat_counts[tid] = 0.0f;
    if (tid < NSUP) sup_counts[tid] = 0.0f;
    // gt_mask dtype probe: int32 0/1 LE => bytes at offset%4!=0 are all zero
    const unsigned char* mb = (const unsigned char*)gt_mask_raw;
    if ((tid & 3) != 0 && mb[tid] != 0) atomicOr(&s_is_u8, 1);
    __syncthreads();

    // ---- grouped greedy resolve: lanes 0..15 each own one 64-bit remv word.
    // Triangular: at group g only lanes >= g hold live words.
    if (tid < 16) {
        const int lane = tid;
        ull remv = 0;
        for (int g = 0; g < 16; g++) {
            ull k64 = 0;
            if (lane == g) {
                ull buf[8];
#pragma unroll
                for (int t = 0; t < 8; t++) buf[t] = smask[(size_t)(g * 64 + t) * 16 + g];
#pragma unroll
                for (int t = 0; t < 64; t++) {
                    ull mrow = buf[t & 7];
                    if (t < 56) buf[t & 7] = smask[(size_t)(g * 64 + t + 8) * 16 + g];
                    if (sval[g * 64 + t] && !((remv >> t) & 1ULL)) {
                        remv |= mrow;
                        k64 |= (1ULL << t);
                    }
                }
            }
            k64 = __shfl_sync(0x0000FFFFu, k64, g);
            if (lane > g) {                       // triangular: words < g are dead
                ull kk = k64;
                while (kk) {
                    int t = __ffsll(kk) - 1;
                    kk &= kk - 1;
                    remv |= smask[(size_t)(g * 64 + t) * 16 + lane];
                }
            }
            if (lane == 0) s_k64[g] = k64;
        }
    }
    __syncthreads();
    if (tid == 0) {
        int r = 0;
        for (int w = 0; w < 16; w++) { s_base[w] = r; r += __popcll(s_k64[w]); }
        s_base[16] = r;
    }
    __syncthreads();
    {
        int w = tid >> 6, t = tid & 63;
        ull kw = s_k64[w];
        int kp = (int)((kw >> t) & 1ULL);
        ull pmask = (t == 63) ? ~0ULL : ((1ULL << (t + 1)) - 1ULL);
        int rank = s_base[w] + __popcll(kw & pmask);     // inclusive cumsum
        int keep = kp && (rank <= MAX_DET);
        int pv = keep && (sconf[tid] > CONF_MATCH);
        spv[tid] = (unsigned char)pv;
        unsigned bal = __ballot_sync(0xFFFFFFFFu, pv);
        if ((tid & 31) == 0) atomicAdd(&s_npred, __popc(bal));
    }
    __syncthreads();

    // ---- GT matching (one warp per GT) ----
    const int g = tid >> 5;
    const int lane = tid & 31;
    const float4 gb = *(const float4*)(gt_boxes + ((size_t)b * NG + g) * 4);
    const int gc = gt_cls[b * NG + g];
    const float garea = (gb.z - gb.x) * (gb.w - gb.y);

    float best = -1.0f;
    int bidx = 0;
#pragma unroll 4
    for (int t = 0; t < KTOP / 32; t++) {
        int i = t * 32 + lane;
        float v = -1.0f;
        if (spv[i] && scls[i] == gc) {
            float4 p = sbox[i];
            float lx = fmaxf(p.x, gb.x);
            float ly = fmaxf(p.y, gb.y);
            float rx = fminf(p.z, gb.z);
            float ry = fminf(p.w, gb.w);
            float iw = fmaxf(rx - lx, 0.0f);
            float ih = fmaxf(ry - ly, 0.0f);
            float inter = iw * ih;
            float pa = (p.z - p.x) * (p.w - p.y);
            v = inter / (pa + garea - inter + 1e-9f);
        }
        if (v > best) { best = v; bidx = i; }   // ascending i per lane -> first max
    }
    for (int off = 16; off > 0; off >>= 1) {
        float ob = __shfl_down_sync(0xFFFFFFFFu, best, off);
        int   oi = __shfl_down_sync(0xFFFFFFFFu, bidx, off);
        if (ob > best || (ob == best && oi < bidx)) { best = ob; bidx = oi; }
    }
    if (lane == 0) {
        int gm;
        if (s_is_u8) gm = (mb[b * NG + g] != 0);
        else         gm = (((const int*)gt_mask_raw)[b * NG + g] != 0);
        s_biou[g]  = best;
        s_bconf[g] = sconf[bidx];
        int hit = (best > IOU_MATCH) && gm;
        s_hit[g] = hit;
        s_gm[g]  = gm;
        if (gm) {
            atomicAdd(&cat_counts[gc], 1.0f);
            atomicAdd(&sup_counts[cat_to_super[gc]], 1.0f);
        }
    }
    __syncthreads();

    if (tid < 32) {
        int gmv = s_gm[tid], hitv = s_hit[tid];
        float si = hitv ? s_biou[tid]  : 0.0f;
        float sc = hitv ? s_bconf[tid] : 0.0f;
        int n_gt = gmv, n_hit = hitv;
        float sum_iou = si, sum_conf = sc;
        for (int off = 16; off > 0; off >>= 1) {
            n_gt     += __shfl_down_sync(0xFFFFFFFFu, n_gt, off);
            n_hit    += __shfl_down_sync(0xFFFFFFFFu, n_hit, off);
            sum_iou  += __shfl_down_sync(0xFFFFFFFFu, sum_iou, off);
            sum_conf += __shfl_down_sync(0xFFFFFFFFu, sum_conf, off);
        }
        if (tid == 0) {
            float fh = (float)n_hit;
            float mean_iou  = sum_iou / fmaxf(fh, 1.0f);
            float mean_conf = (n_hit > 0) ? (sum_conf / fmaxf(fh, 1.0f)) : 1.0f;
            float correct   = fh / fmaxf((float)n_gt, 1.0f);
            float bc = cat_counts[0]; int mfc = 0;
            for (int c = 1; c < NC; c++)
                if (cat_counts[c] > bc) { bc = cat_counts[c]; mfc = c; }
            float bs = sup_counts[0]; int mfs = 0;
            for (int s = 1; s < NSUP; s++)
                if (sup_counts[s] > bs) { bs = sup_counts[s]; mfs = s; }
            float r0, r1, r2, r3, r4;
            if (n_gt == 0) {
                if (s_npred == 0) { r0 = 1.0f; r1 = 1.0f; r2 = -1.0f; r3 = -1.0f; r4 = 1.0f; }
                else              { r0 = 0.0f; r1 = 1.0f; r2 = -2.0f; r3 = -2.0f; r4 = 0.0f; }
            } else {
                r0 = mean_iou; r1 = mean_conf; r2 = (float)mfc; r3 = (float)mfs; r4 = correct;
            }
            out[b * 5 + 0] = r0;
            out[b * 5 + 1] = r1;
            out[b * 5 + 2] = r2;
            out[b * 5 + 3] = r3;
            out[b * 5 + 4] = r4;
        }
    }
}

// ---------------- launch -----------------------------------------------------------
extern "C" void kernel_launch(void* const* d_in, const int* in_sizes, int n_in,
                              void* d_out, int out_size) {
    const float* preds        = (const float*)d_in[0];
    const float* gt_boxes     = (const float*)d_in[1];
    const int*   gt_cls       = (const int*)d_in[2];
    const void*  gt_mask      = (const void*)d_in[3];
    const int*   cat_to_super = (const int*)d_in[4];
    float* out = (float*)d_out;

    (void)in_sizes; (void)n_in; (void)out_size;

    cudaFuncSetAttribute(k_resolve_match,
                         cudaFuncAttributeMaxDynamicSharedMemorySize,
                         KTOP * 16 * (int)sizeof(ull));

    k_decode<<<(NB * NA) / 256, 256>>>(preds);            // exact: 1050 blocks
    k_select<<<NB, 1024, CAP * sizeof(ull)>>>(preds);
    k_nmsmask<<<dim3(36, NB), 256>>>();
    k_resolve_match<<<NB, 1024, KTOP * 16 * sizeof(ull)>>>(gt_boxes, gt_cls, gt_mask,
                                                           cat_to_super, out);
}

// round 10
// speedup vs baseline: 1.4106x; 1.4106x over previous
#include <cuda_runtime.h>
#include <cstdint>

typedef unsigned long long ull;

#define NB 32
#define NA 8400
#define NC 80
#define KTOP 1024
#define NG 32
#define NSUP 16
#define MAX_DET 300
#define CONF_NMS 0.25f
#define IOU_NMS 0.45f
#define CONF_MATCH 0.5f
#define IOU_MATCH 0.6f
#define MAX_WH 7680.0f

// histogram select parameters: bucket = 1 + ((fb - 0x3E800000) >> 11), monotone in conf
#define FB_BASE 0x3E800000u
#define BSHIFT 11
#define NBPAD 9216          // 1024 threads * CH chunks, covers 8193 buckets
#define CH 9
#define CAP 2048            // gather capacity / sort size (expected ~1100)

// ---------------- scratch (global __device__ arrays; no allocation) ----------------
__device__ unsigned               g_hist[NB * NBPAD];   // zero-init; k_select re-zeroes
__device__ __align__(16) float    g_conf[NB * NA];
__device__ __align__(16) int      g_cls[NB * NA];
__device__ float4                 g_box4[NB * KTOP];    // unshifted x1y1x2y2
__device__ float4                 g_sbox4[NB * KTOP];   // class-shifted
__device__ float                  g_area[NB * KTOP];    // area of shifted box
__device__ float                  g_conf_k[NB * KTOP];
__device__ int                    g_cls_k[NB * KTOP];
__device__ __align__(16) ull      g_mask[NB * KTOP * 16];

// upper-triangle 128x128 tile pairs (tr <= tc) over 8 tiles
__device__ const unsigned char c_tr[36] =
    {0,0,0,0,0,0,0,0, 1,1,1,1,1,1,1, 2,2,2,2,2,2, 3,3,3,3,3, 4,4,4,4, 5,5,5, 6,6, 7};
__device__ const unsigned char c_tc[36] =
    {0,1,2,3,4,5,6,7, 1,2,3,4,5,6,7, 2,3,4,5,6,7, 3,4,5,6,7, 4,5,6,7, 5,6,7, 6,7, 7};

__device__ __forceinline__ int conf_bucket(float c) {
    if (c <= 0.0f) return 0;
    unsigned fb = __float_as_uint(c);
    return 1 + (int)((fb - FB_BASE) >> BSHIFT);
}

// ---------------- Kernel 1: decode conf/cls (vectorized x4) + histogram ------------
__global__ void k_decode(const float* __restrict__ preds) {
    int t = blockIdx.x * blockDim.x + threadIdx.x;
    if (t >= NB * (NA / 4)) return;
    int b = t / (NA / 4);
    int a4 = (t - b * (NA / 4)) * 4;
    const float* base = preds + (size_t)b * 84 * NA;

    float4 m = *(const float4*)(base + (size_t)4 * NA + a4);
    int ax = 0, ay = 0, az = 0, aw = 0;
#pragma unroll 4
    for (int c = 1; c < NC; c++) {
        float4 v = *(const float4*)(base + (size_t)(4 + c) * NA + a4);
        if (v.x > m.x) { m.x = v.x; ax = c; }   // strict > keeps FIRST max
        if (v.y > m.y) { m.y = v.y; ay = c; }
        if (v.z > m.z) { m.z = v.z; az = c; }
        if (v.w > m.w) { m.w = v.w; aw = c; }
    }
    m.x = (m.x > CONF_NMS) ? m.x : 0.0f;
    m.y = (m.y > CONF_NMS) ? m.y : 0.0f;
    m.z = (m.z > CONF_NMS) ? m.z : 0.0f;
    m.w = (m.w > CONF_NMS) ? m.w : 0.0f;

    *(float4*)&g_conf[b * NA + a4] = m;
    *(int4*)&g_cls[b * NA + a4] = make_int4(ax, ay, az, aw);

    unsigned* h = &g_hist[b * NBPAD];
    atomicAdd(&h[conf_bucket(m.x)], 1u);
    atomicAdd(&h[conf_bucket(m.y)], 1u);
    atomicAdd(&h[conf_bucket(m.z)], 1u);
    atomicAdd(&h[conf_bucket(m.w)], 1u);
}

// ---------------- Kernel 2: histogram select + bitonic sort of <=2048 candidates ---
// keys = (~float_bits(conf) << 32) | index : ascending sort == conf desc, idx asc
// (identical ordering to lax.top_k incl. ties)
__global__ __launch_bounds__(1024, 1) void k_select(const float* __restrict__ preds) {
    extern __shared__ ull skey[];               // CAP entries
    __shared__ unsigned s_suf[1024];
    __shared__ int s_bstar;
    __shared__ int s_cnt;

    const int b = blockIdx.x;
    const int tid = threadIdx.x;
    const int q0 = tid * CH;

    // chunk sums
    unsigned v = 0;
#pragma unroll
    for (int k = 0; k < CH; k++) v += g_hist[b * NBPAD + q0 + k];
    s_suf[tid] = v;
    __syncthreads();
    // inclusive suffix scan (Hillis-Steele)
    for (int d = 1; d < 1024; d <<= 1) {
        unsigned add = (tid + d < 1024) ? s_suf[tid + d] : 0u;
        __syncthreads();
        v += add;
        s_suf[tid] = v;
        __syncthreads();
    }
    // unique crossing thread finds threshold bucket B*: largest bucket with
    // count(buckets >= B*) >= KTOP
    unsigned nxt = (tid < 1023) ? s_suf[tid + 1] : 0u;
    if (s_suf[tid] >= KTOP && !(tid < 1023 && nxt >= KTOP)) {
        unsigned running = nxt;
        int B = q0;
        for (int q = q0 + CH - 1; q >= q0; q--) {
            running += g_hist[b * NBPAD + q];
            if (running >= KTOP) { B = q; break; }
        }
        s_bstar = B;
    }
    if (tid == 0) s_cnt = 0;
    for (int i = tid; i < CAP; i += 1024) skey[i] = ~0ULL;   // padding sorts last
    __syncthreads();

    // hist fully consumed -> re-zero for the next graph replay
    for (int i = tid; i < NBPAD; i += 1024) g_hist[b * NBPAD + i] = 0u;

    const int Bs = s_bstar;
    for (int i = tid; i < NA; i += 1024) {
        float c = g_conf[b * NA + i];
        if (conf_bucket(c) >= Bs) {
            int p = atomicAdd(&s_cnt, 1);
            if (p < CAP)
                skey[p] = ((ull)(~__float_as_uint(c)) << 32) | (unsigned)i;
        }
    }
    __syncthreads();

    // bitonic sort of CAP keys
    for (unsigned k = 2; k <= CAP; k <<= 1) {
        for (unsigned j = k >> 1; j > 0; j >>= 1) {
#pragma unroll 1
            for (unsigned i = tid; i < CAP; i += 1024) {
                unsigned ixj = i ^ j;
                if (ixj > i) {
                    ull x = skey[i];
                    ull y = skey[ixj];
                    bool up = ((i & k) == 0);
                    if (up ? (x > y) : (x < y)) { skey[i] = y; skey[ixj] = x; }
                }
            }
            __syncthreads();
        }
    }

    // emit top-KTOP (guaranteed >= KTOP gathered)
    ull key = skey[tid];
    unsigned fb = ~(unsigned)(key >> 32);
    float conf = __uint_as_float(fb);
    int a = (int)(key & 0xFFFFFFFFu);
    const float* base = preds + (size_t)b * 84 * NA;
    float cx = base[a];
    float cy = base[NA + a];
    float w  = base[2 * NA + a];
    float h  = base[3 * NA + a];
    float x1 = cx - w * 0.5f, y1 = cy - h * 0.5f;
    float x2 = cx + w * 0.5f, y2 = cy + h * 0.5f;
    int o = b * KTOP + tid;
    int cls = g_cls[b * NA + a];
    float sh = (float)cls * MAX_WH;
    float sx1 = x1 + sh, sy1 = y1 + sh, sx2 = x2 + sh, sy2 = y2 + sh;
    g_box4[o]  = make_float4(x1, y1, x2, y2);
    g_sbox4[o] = make_float4(sx1, sy1, sx2, sy2);
    g_area[o]  = (sx2 - sx1) * (sy2 - sy1);     // area AFTER shift (bit-matches ref)
    g_conf_k[o] = conf;
    g_cls_k[o]  = cls;
}

// ---------------- Kernel 3: NMS IoU bit-mask, upper triangle only, ballot-based ----
__global__ __launch_bounds__(256) void k_nmsmask() {
    __shared__ float4 srow[128];
    __shared__ float  sarea[128];
    const int b = blockIdx.y;
    const int tr = c_tr[blockIdx.x];
    const int tc = c_tc[blockIdx.x];
    const int tid = threadIdx.x;
    const int lane = tid & 31;
    const int w = tid >> 5;

    if (tid < 128) {
        srow[tid]  = g_sbox4[b * KTOP + tr * 128 + tid];
        sarea[tid] = g_area[b * KTOP + tr * 128 + tid];
    }
    float4 cb[4];
    float  ca[4];
#pragma unroll
    for (int cc = 0; cc < 4; cc++) {
        int j = tc * 128 + cc * 32 + lane;
        cb[cc] = g_sbox4[b * KTOP + j];
        ca[cc] = g_area[b * KTOP + j];
    }
    __syncthreads();

    const bool diag = (tr == tc);
#pragma unroll 4
    for (int rr = 0; rr < 16; rr++) {
        int rl = rr * 8 + w;
        int row = tr * 128 + rl;
        float4 bi = srow[rl];
        float  ai = sarea[rl];
        unsigned bl[4] = {0u, 0u, 0u, 0u};
        bool skip_lo = diag && (rr >= 8);    // rows >= 64 of diag tile: word 2*tc dead
#pragma unroll
        for (int cc = 0; cc < 4; cc++) {
            if (skip_lo && cc < 2) continue;              // warp-uniform skip
            float4 bj = cb[cc];
            float lx = fmaxf(bi.x, bj.x);
            float ly = fmaxf(bi.y, bj.y);
            float rx = fminf(bi.z, bj.z);
            float ry = fminf(bi.w, bj.w);
            float iw = fmaxf(rx - lx, 0.0f);
            float ih = fmaxf(ry - ly, 0.0f);
            float inter = iw * ih;
            float iou = inter / (ai + ca[cc] - inter + 1e-9f);   // same arithmetic
            bl[cc] = __ballot_sync(0xFFFFFFFFu, iou > IOU_NMS);
        }
        ull* mrow = &g_mask[((size_t)b * KTOP + row) * 16];
        if (!skip_lo) {
            if (lane == 0) mrow[2 * tc]     = (ull)bl[0] | ((ull)bl[1] << 32);
            if (lane == 1) mrow[2 * tc + 1] = (ull)bl[2] | ((ull)bl[3] << 32);
        } else {
            if (lane == 1) mrow[2 * tc + 1] = (ull)bl[2] | ((ull)bl[3] << 32);
        }
    }
}

// ---------------- Kernel 4: grouped NMS resolve (branchless) + GT match ------------
__global__ __launch_bounds__(1024, 1) void k_resolve_match(
        const float* __restrict__ gt_boxes,
        const int* __restrict__ gt_cls,
        const void* __restrict__ gt_mask_raw,
        const int* __restrict__ cat_to_super,
        float* __restrict__ out) {
    extern __shared__ char dyn[];
    ull* smask = (ull*)dyn;                   // KTOP*16 u64 = 128 KB

    __shared__ float4 sbox[KTOP];
    __shared__ float  sconf[KTOP];
    __shared__ int    scls[KTOP];
    __shared__ unsigned char spv[KTOP];
    __shared__ unsigned s_bal[32];            // per-warp validity ballots
    __shared__ ull    s_val64[16];
    __shared__ ull    s_k64[16];
    __shared__ int    s_base[17];
    __shared__ float  s_biou[NG];
    __shared__ float  s_bconf[NG];
    __shared__ int    s_hit[NG];
    __shared__ int    s_gm[NG];
    __shared__ float  cat_counts[NC];
    __shared__ float  sup_counts[NSUP];
    __shared__ int    s_npred;
    __shared__ int    s_is_u8;

    const int b = blockIdx.x;
    const int tid = threadIdx.x;
    const int o = b * KTOP + tid;

    // bulk copy mask batch-slice into smem (coalesced; lower-triangle words are
    // garbage but never read)
    const float4* msrc = (const float4*)(g_mask + (size_t)b * KTOP * 16);
    float4* mdst = (float4*)smask;
#pragma unroll
    for (int i = 0; i < 8; i++) mdst[tid + i * 1024] = msrc[tid + i * 1024];

    float cf = g_conf_k[o];
    sbox[tid]  = g_box4[o];
    sconf[tid] = cf;
    scls[tid]  = g_cls_k[o];
    // validity bits packed via ballot: group g valid64 = warp 2g | warp 2g+1 << 32
    {
        unsigned bal = __ballot_sync(0xFFFFFFFFu, cf > 0.0f);
        if ((tid & 31) == 0) s_bal[tid >> 5] = bal;
    }
    if (tid == 0) { s_npred = 0; s_is_u8 = 0; }
    if (tid < NC)   cat_counts[tid] = 0.0f;
    if (tid < NSUP) sup_counts[tid] = 0.0f;
    // gt_mask dtype probe: int32 0/1 LE => bytes at offset%4!=0 are all zero
    const unsigned char* mb = (const unsigned char*)gt_mask_raw;
    if ((tid & 3) != 0 && mb[tid] != 0) atomicOr(&s_is_u8, 1);
    __syncthreads();
    if (tid < 16)
        s_val64[tid] = (ull)s_bal[2 * tid] | ((ull)s_bal[2 * tid + 1] << 32);
    __syncthreads();

    // ---- grouped greedy resolve: lanes 0..15 each own one 64-bit remv word.
    // Owner chain is branchless register arithmetic; mask rows prefetched.
    if (tid < 16) {
        const int lane = tid;
        ull remv = 0;
        for (int g = 0; g < 16; g++) {
            ull k64 = 0;
            if (lane == g) {
                const ull valid = s_val64[g];
                ull buf[8];
#pragma unroll
                for (int t = 0; t < 8; t++) buf[t] = smask[(size_t)(g * 64 + t) * 16 + g];
#pragma unroll
                for (int t = 0; t < 64; t++) {
                    ull mrow = buf[t & 7];
                    if (t < 56) buf[t & 7] = smask[(size_t)(g * 64 + t + 8) * 16 + g];
                    ull nb = ((valid & ~remv) >> t) & 1ULL;   // take-bit
                    remv |= mrow & (0ULL - nb);
                    k64  |= nb << t;
                }
            }
            k64 = __shfl_sync(0x0000FFFFu, k64, g);
            if (lane > g) {                       // triangular: words < g are dead
                ull kk = k64;
                while (kk) {
                    int t = __ffsll(kk) - 1;
                    kk &= kk - 1;
                    remv |= smask[(size_t)(g * 64 + t) * 16 + lane];
                }
            }
            if (lane == 0) s_k64[g] = k64;
        }
    }
    __syncthreads();
    if (tid == 0) {
        int r = 0;
        for (int w = 0; w < 16; w++) { s_base[w] = r; r += __popcll(s_k64[w]); }
        s_base[16] = r;
    }
    __syncthreads();
    {
        int w = tid >> 6, t = tid & 63;
        ull kw = s_k64[w];
        int kp = (int)((kw >> t) & 1ULL);
        ull pmask = (t == 63) ? ~0ULL : ((1ULL << (t + 1)) - 1ULL);
        int rank = s_base[w] + __popcll(kw & pmask);     // inclusive cumsum
        int keep = kp && (rank <= MAX_DET);
        int pv = keep && (sconf[tid] > CONF_MATCH);
        spv[tid] = (unsigned char)pv;
        unsigned bal = __ballot_sync(0xFFFFFFFFu, pv);
        if ((tid & 31) == 0) atomicAdd(&s_npred, __popc(bal));
    }
    __syncthreads();

    // ---- GT matching (one warp per GT) ----
    const int g = tid >> 5;
    const int lane = tid & 31;
    const float4 gb = *(const float4*)(gt_boxes + ((size_t)b * NG + g) * 4);
    const int gc = gt_cls[b * NG + g];
    const float garea = (gb.z - gb.x) * (gb.w - gb.y);

    float best = -1.0f;
    int bidx = 0;
#pragma unroll 4
    for (int t = 0; t < KTOP / 32; t++) {
        int i = t * 32 + lane;
        float v = -1.0f;
        if (spv[i] && scls[i] == gc) {
            float4 p = sbox[i];
            float lx = fmaxf(p.x, gb.x);
            float ly = fmaxf(p.y, gb.y);
            float rx = fminf(p.z, gb.z);
            float ry = fminf(p.w, gb.w);
            float iw = fmaxf(rx - lx, 0.0f);
            float ih = fmaxf(ry - ly, 0.0f);
            float inter = iw * ih;
            float pa = (p.z - p.x) * (p.w - p.y);
            v = inter / (pa + garea - inter + 1e-9f);
        }
        if (v > best) { best = v; bidx = i; }   // ascending i per lane -> first max
    }
    for (int off = 16; off > 0; off >>= 1) {
        float ob = __shfl_down_sync(0xFFFFFFFFu, best, off);
        int   oi = __shfl_down_sync(0xFFFFFFFFu, bidx, off);
        if (ob > best || (ob == best && oi < bidx)) { best = ob; bidx = oi; }
    }
    if (lane == 0) {
        int gm;
        if (s_is_u8) gm = (mb[b * NG + g] != 0);
        else         gm = (((const int*)gt_mask_raw)[b * NG + g] != 0);
        s_biou[g]  = best;
        s_bconf[g] = sconf[bidx];
        int hit = (best > IOU_MATCH) && gm;
        s_hit[g] = hit;
        s_gm[g]  = gm;
        if (gm) {
            atomicAdd(&cat_counts[gc], 1.0f);
            atomicAdd(&sup_counts[cat_to_super[gc]], 1.0f);
        }
    }
    __syncthreads();

    if (tid < 32) {
        int gmv = s_gm[tid], hitv = s_hit[tid];
        float si = hitv ? s_biou[tid]  : 0.0f;
        float sc = hitv ? s_bconf[tid] : 0.0f;
        int n_gt = gmv, n_hit = hitv;
        float sum_iou = si, sum_conf = sc;
        for (int off = 16; off > 0; off >>= 1) {
            n_gt     += __shfl_down_sync(0xFFFFFFFFu, n_gt, off);
            n_hit    += __shfl_down_sync(0xFFFFFFFFu, n_hit, off);
            sum_iou  += __shfl_down_sync(0xFFFFFFFFu, sum_iou, off);
            sum_conf += __shfl_down_sync(0xFFFFFFFFu, sum_conf, off);
        }
        if (tid == 0) {
            float fh = (float)n_hit;
            float mean_iou  = sum_iou / fmaxf(fh, 1.0f);
            float mean_conf = (n_hit > 0) ? (sum_conf / fmaxf(fh, 1.0f)) : 1.0f;
            float correct   = fh / fmaxf((float)n_gt, 1.0f);
            float bc = cat_counts[0]; int mfc = 0;
            for (int c = 1; c < NC; c++)
                if (cat_counts[c] > bc) { bc = cat_counts[c]; mfc = c; }
            float bs = sup_counts[0]; int mfs = 0;
            for (int s = 1; s < NSUP; s++)
                if (sup_counts[s] > bs) { bs = sup_counts[s]; mfs = s; }
            float r0, r1, r2, r3, r4;
            if (n_gt == 0) {
                if (s_npred == 0) { r0 = 1.0f; r1 = 1.0f; r2 = -1.0f; r3 = -1.0f; r4 = 1.0f; }
                else              { r0 = 0.0f; r1 = 1.0f; r2 = -2.0f; r3 = -2.0f; r4 = 0.0f; }
            } else {
                r0 = mean_iou; r1 = mean_conf; r2 = (float)mfc; r3 = (float)mfs; r4 = correct;
            }
            out[b * 5 + 0] = r0;
            out[b * 5 + 1] = r1;
            out[b * 5 + 2] = r2;
            out[b * 5 + 3] = r3;
            out[b * 5 + 4] = r4;
        }
    }
}

// ---------------- launch -----------------------------------------------------------
extern "C" void kernel_launch(void* const* d_in, const int* in_sizes, int n_in,
                              void* d_out, int out_size) {
    const float* preds        = (const float*)d_in[0];
    const float* gt_boxes     = (const float*)d_in[1];
    const int*   gt_cls       = (const int*)d_in[2];
    const void*  gt_mask      = (const void*)d_in[3];
    const int*   cat_to_super = (const int*)d_in[4];
    float* out = (float*)d_out;

    (void)in_sizes; (void)n_in; (void)out_size;

    cudaFuncSetAttribute(k_resolve_match,
                         cudaFuncAttributeMaxDynamicSharedMemorySize,
                         KTOP * 16 * (int)sizeof(ull));

    k_decode<<<(NB * (NA / 4) + 255) / 256, 256>>>(preds);
    k_select<<<NB, 1024, CAP * sizeof(ull)>>>(preds);
    k_nmsmask<<<dim3(36, NB), 256>>>();
    k_resolve_match<<<NB, 1024, KTOP * 16 * sizeof(ull)>>>(gt_boxes, gt_cls, gt_mask,
                                                           cat_to_super, out);
}

// round 12
// speedup vs baseline: 2.3181x; 1.6434x over previous
#include <cuda_runtime.h>
#include <cstdint>

typedef unsigned long long ull;

#define NB 32
#define NA 8400
#define NC 80
#define KTOP 1024
#define NG 32
#define NSUP 16
#define MAX_DET 300
#define CONF_NMS 0.25f
#define IOU_NMS 0.45f
#define CONF_MATCH 0.5f
#define IOU_MATCH 0.6f
#define MAX_WH 7680.0f

// histogram select parameters: bucket = 1 + ((fb - 0x3E800000) >> 11), monotone in conf
#define FB_BASE 0x3E800000u
#define BSHIFT 11
#define NBPAD 9216          // 1024 threads * CH chunks, covers 8193 buckets
#define CH 9
#define CAP 2048            // gather capacity / sort size (expected ~1100)

// ---------------- scratch (global __device__ arrays; no allocation) ----------------
__device__ unsigned               g_hist[NB * NBPAD];   // zero-init; k_select re-zeroes
__device__ __align__(16) float    g_conf[NB * NA];
__device__ __align__(16) int      g_cls[NB * NA];
__device__ float4                 g_box4[NB * KTOP];    // unshifted x1y1x2y2
__device__ float4                 g_sbox4[NB * KTOP];   // class-shifted
__device__ float                  g_area[NB * KTOP];    // area of shifted box
__device__ float                  g_conf_k[NB * KTOP];
__device__ int                    g_cls_k[NB * KTOP];
__device__ __align__(16) ull      g_mask[NB * KTOP * 16];

// upper-triangle 128x128 tile pairs (tr <= tc) over 8 tiles
__device__ const unsigned char c_tr[36] =
    {0,0,0,0,0,0,0,0, 1,1,1,1,1,1,1, 2,2,2,2,2,2, 3,3,3,3,3, 4,4,4,4, 5,5,5, 6,6, 7};
__device__ const unsigned char c_tc[36] =
    {0,1,2,3,4,5,6,7, 1,2,3,4,5,6,7, 2,3,4,5,6,7, 3,4,5,6,7, 4,5,6,7, 5,6,7, 6,7, 7};

__device__ __forceinline__ int conf_bucket(float c) {
    if (c <= 0.0f) return 0;
    unsigned fb = __float_as_uint(c);
    return 1 + (int)((fb - FB_BASE) >> BSHIFT);
}

// ---------------- Kernel 1: decode conf/cls (vectorized x4) + histogram ------------
__global__ void k_decode(const float* __restrict__ preds) {
    int t = blockIdx.x * blockDim.x + threadIdx.x;
    if (t >= NB * (NA / 4)) return;
    int b = t / (NA / 4);
    int a4 = (t - b * (NA / 4)) * 4;
    const float* base = preds + (size_t)b * 84 * NA;

    float4 m = *(const float4*)(base + (size_t)4 * NA + a4);
    int ax = 0, ay = 0, az = 0, aw = 0;
#pragma unroll 4
    for (int c = 1; c < NC; c++) {
        float4 v = *(const float4*)(base + (size_t)(4 + c) * NA + a4);
        if (v.x > m.x) { m.x = v.x; ax = c; }   // strict > keeps FIRST max
        if (v.y > m.y) { m.y = v.y; ay = c; }
        if (v.z > m.z) { m.z = v.z; az = c; }
        if (v.w > m.w) { m.w = v.w; aw = c; }
    }
    m.x = (m.x > CONF_NMS) ? m.x : 0.0f;
    m.y = (m.y > CONF_NMS) ? m.y : 0.0f;
    m.z = (m.z > CONF_NMS) ? m.z : 0.0f;
    m.w = (m.w > CONF_NMS) ? m.w : 0.0f;

    *(float4*)&g_conf[b * NA + a4] = m;
    *(int4*)&g_cls[b * NA + a4] = make_int4(ax, ay, az, aw);

    unsigned* h = &g_hist[b * NBPAD];
    atomicAdd(&h[conf_bucket(m.x)], 1u);
    atomicAdd(&h[conf_bucket(m.y)], 1u);
    atomicAdd(&h[conf_bucket(m.z)], 1u);
    atomicAdd(&h[conf_bucket(m.w)], 1u);
}

// ---------------- Kernel 2: histogram select + bitonic sort of <=2048 candidates ---
// keys = (~float_bits(conf) << 32) | index : ascending sort == conf desc, idx asc
// (identical ordering to lax.top_k incl. ties)
__global__ __launch_bounds__(1024, 1) void k_select(const float* __restrict__ preds) {
    extern __shared__ ull skey[];               // CAP entries
    __shared__ unsigned s_suf[1024];
    __shared__ int s_bstar;
    __shared__ int s_cnt;

    const int b = blockIdx.x;
    const int tid = threadIdx.x;
    const int q0 = tid * CH;

    // chunk sums
    unsigned v = 0;
#pragma unroll
    for (int k = 0; k < CH; k++) v += g_hist[b * NBPAD + q0 + k];
    s_suf[tid] = v;
    __syncthreads();
    // inclusive suffix scan (Hillis-Steele)
    for (int d = 1; d < 1024; d <<= 1) {
        unsigned add = (tid + d < 1024) ? s_suf[tid + d] : 0u;
        __syncthreads();
        v += add;
        s_suf[tid] = v;
        __syncthreads();
    }
    // unique crossing thread finds threshold bucket B*: largest bucket with
    // count(buckets >= B*) >= KTOP
    unsigned nxt = (tid < 1023) ? s_suf[tid + 1] : 0u;
    if (s_suf[tid] >= KTOP && !(tid < 1023 && nxt >= KTOP)) {
        unsigned running = nxt;
        int B = q0;
        for (int q = q0 + CH - 1; q >= q0; q--) {
            running += g_hist[b * NBPAD + q];
            if (running >= KTOP) { B = q; break; }
        }
        s_bstar = B;
    }
    if (tid == 0) s_cnt = 0;
    for (int i = tid; i < CAP; i += 1024) skey[i] = ~0ULL;   // padding sorts last
    __syncthreads();

    // hist fully consumed -> re-zero for the next graph replay
    for (int i = tid; i < NBPAD; i += 1024) g_hist[b * NBPAD + i] = 0u;

    const int Bs = s_bstar;
    for (int i = tid; i < NA; i += 1024) {
        float c = g_conf[b * NA + i];
        if (conf_bucket(c) >= Bs) {
            int p = atomicAdd(&s_cnt, 1);
            if (p < CAP)
                skey[p] = ((ull)(~__float_as_uint(c)) << 32) | (unsigned)i;
        }
    }
    __syncthreads();

    // bitonic sort of CAP keys
    for (unsigned k = 2; k <= CAP; k <<= 1) {
        for (unsigned j = k >> 1; j > 0; j >>= 1) {
#pragma unroll 1
            for (unsigned i = tid; i < CAP; i += 1024) {
                unsigned ixj = i ^ j;
                if (ixj > i) {
                    ull x = skey[i];
                    ull y = skey[ixj];
                    bool up = ((i & k) == 0);
                    if (up ? (x > y) : (x < y)) { skey[i] = y; skey[ixj] = x; }
                }
            }
            __syncthreads();
        }
    }

    // emit top-KTOP (guaranteed >= KTOP gathered)
    ull key = skey[tid];
    unsigned fb = ~(unsigned)(key >> 32);
    float conf = __uint_as_float(fb);
    int a = (int)(key & 0xFFFFFFFFu);
    const float* base = preds + (size_t)b * 84 * NA;
    float cx = base[a];
    float cy = base[NA + a];
    float w  = base[2 * NA + a];
    float h  = base[3 * NA + a];
    float x1 = cx - w * 0.5f, y1 = cy - h * 0.5f;
    float x2 = cx + w * 0.5f, y2 = cy + h * 0.5f;
    int o = b * KTOP + tid;
    int cls = g_cls[b * NA + a];
    float sh = (float)cls * MAX_WH;
    float sx1 = x1 + sh, sy1 = y1 + sh, sx2 = x2 + sh, sy2 = y2 + sh;
    g_box4[o]  = make_float4(x1, y1, x2, y2);
    g_sbox4[o] = make_float4(sx1, sy1, sx2, sy2);
    g_area[o]  = (sx2 - sx1) * (sy2 - sy1);     // area AFTER shift (bit-matches ref)
    g_conf_k[o] = conf;
    g_cls_k[o]  = cls;
}

// ---------------- Kernel 3: NMS IoU bit-mask, upper triangle only, ballot-based ----
__global__ __launch_bounds__(256) void k_nmsmask() {
    __shared__ float4 srow[128];
    __shared__ float  sarea[128];
    const int b = blockIdx.y;
    const int tr = c_tr[blockIdx.x];
    const int tc = c_tc[blockIdx.x];
    const int tid = threadIdx.x;
    const int lane = tid & 31;
    const int w = tid >> 5;

    if (tid < 128) {
        srow[tid]  = g_sbox4[b * KTOP + tr * 128 + tid];
        sarea[tid] = g_area[b * KTOP + tr * 128 + tid];
    }
    float4 cb[4];
    float  ca[4];
#pragma unroll
    for (int cc = 0; cc < 4; cc++) {
        int j = tc * 128 + cc * 32 + lane;
        cb[cc] = g_sbox4[b * KTOP + j];
        ca[cc] = g_area[b * KTOP + j];
    }
    __syncthreads();

    const bool diag = (tr == tc);
#pragma unroll 4
    for (int rr = 0; rr < 16; rr++) {
        int rl = rr * 8 + w;
        int row = tr * 128 + rl;
        float4 bi = srow[rl];
        float  ai = sarea[rl];
        unsigned bl[4] = {0u, 0u, 0u, 0u};
        bool skip_lo = diag && (rr >= 8);    // rows >= 64 of diag tile: word 2*tc dead
#pragma unroll
        for (int cc = 0; cc < 4; cc++) {
            if (skip_lo && cc < 2) continue;              // warp-uniform skip
            float4 bj = cb[cc];
            float lx = fmaxf(bi.x, bj.x);
            float ly = fmaxf(bi.y, bj.y);
            float rx = fminf(bi.z, bj.z);
            float ry = fminf(bi.w, bj.w);
            float iw = fmaxf(rx - lx, 0.0f);
            float ih = fmaxf(ry - ly, 0.0f);
            float inter = iw * ih;
            float iou = inter / (ai + ca[cc] - inter + 1e-9f);   // same arithmetic
            bl[cc] = __ballot_sync(0xFFFFFFFFu, iou > IOU_NMS);
        }
        ull* mrow = &g_mask[((size_t)b * KTOP + row) * 16];
        if (!skip_lo) {
            if (lane == 0) mrow[2 * tc]     = (ull)bl[0] | ((ull)bl[1] << 32);
            if (lane == 1) mrow[2 * tc + 1] = (ull)bl[2] | ((ull)bl[3] << 32);
        } else {
            if (lane == 1) mrow[2 * tc + 1] = (ull)bl[2] | ((ull)bl[3] << 32);
        }
    }
}

// ---------------- Kernel 4: fixpoint NMS resolve (parallel, exact) + GT match ------
// Greedy keep is the UNIQUE fixpoint of
//   F(K)[i] = valid[i] && !exists j<i: K[j] && iou(i,j)>thr,
// and F^k is exact on the first k indices from any start, so iterating until
// K == F(K) yields exactly the greedy result (converges in ~3-5 iters here).
__global__ __launch_bounds__(1024, 1) void k_resolve_match(
        const float* __restrict__ gt_boxes,
        const int* __restrict__ gt_cls,
        const void* __restrict__ gt_mask_raw,
        const int* __restrict__ cat_to_super,
        float* __restrict__ out) {
    extern __shared__ char dyn[];
    ull* smask = (ull*)dyn;                   // KTOP*16 u64 = 128 KB

    __shared__ float4 sbox[KTOP];
    __shared__ float  sconf[KTOP];
    __shared__ int    scls[KTOP];
    __shared__ unsigned char spv[KTOP];
    __shared__ unsigned s_bal[32];            // per-warp keep ballots
    __shared__ ull    s_k64[16];              // current keep words
    __shared__ int    s_base[17];
    __shared__ int    s_changed;
    __shared__ float  s_biou[NG];
    __shared__ float  s_bconf[NG];
    __shared__ int    s_hit[NG];
    __shared__ int    s_gm[NG];
    __shared__ float  cat_counts[NC];
    __shared__ float  sup_counts[NSUP];
    __shared__ int    s_npred;
    __shared__ int    s_is_u8;

    const int b = blockIdx.x;
    const int tid = threadIdx.x;
    const int o = b * KTOP + tid;

    // bulk copy mask batch-slice into smem (coalesced; lower-triangle words are
    // garbage but never read)
    const float4* msrc = (const float4*)(g_mask + (size_t)b * KTOP * 16);
    float4* mdst = (float4*)smask;
#pragma unroll
    for (int i = 0; i < 8; i++) mdst[tid + i * 1024] = msrc[tid + i * 1024];

    float cf = g_conf_k[o];
    sbox[tid]  = g_box4[o];
    sconf[tid] = cf;
    scls[tid]  = g_cls_k[o];
    const bool valid = (cf > 0.0f);
    // initial K0 = valid
    {
        unsigned bal = __ballot_sync(0xFFFFFFFFu, valid);
        if ((tid & 31) == 0) s_bal[tid >> 5] = bal;
    }
    if (tid == 0) { s_npred = 0; s_is_u8 = 0; }
    if (tid < NC)   cat_counts[tid] = 0.0f;
    if (tid < NSUP) sup_counts[tid] = 0.0f;
    // gt_mask dtype probe: int32 0/1 LE => bytes at offset%4!=0 are all zero
    const unsigned char* mb = (const unsigned char*)gt_mask_raw;
    if ((tid & 3) != 0 && mb[tid] != 0) atomicOr(&s_is_u8, 1);
    __syncthreads();
    if (tid < 16)
        s_k64[tid] = (ull)s_bal[2 * tid] | ((ull)s_bal[2 * tid + 1] << 32);
    __syncthreads();

    // ---- fixpoint iteration ----
    const int w_i = tid >> 6;
    const int b_i = tid & 63;
    const ull selfmask = (1ULL << b_i) - 1ULL;   // bits strictly below i in own word
    const ull* myrow = smask + (size_t)tid * 16;

    for (;;) {
        ull sup = 0;
#pragma unroll 1
        for (int w = 0; w < w_i; w++) sup |= myrow[w] & s_k64[w];
        sup |= myrow[w_i] & s_k64[w_i] & selfmask;
        bool nk = valid && (sup == 0ULL);
        unsigned bal = __ballot_sync(0xFFFFFFFFu, nk);
        if ((tid & 31) == 0) s_bal[tid >> 5] = bal;
        __syncthreads();                 // all reads of s_k64 done; ballots visible
        if (tid == 0) s_changed = 0;
        __syncthreads();
        if (tid < 16) {
            ull nw = (ull)s_bal[2 * tid] | ((ull)s_bal[2 * tid + 1] << 32);
            if (nw != s_k64[tid]) { s_changed = 1; s_k64[tid] = nw; }
        }
        __syncthreads();
        if (!s_changed) break;
    }

    if (tid == 0) {
        int r = 0;
        for (int w = 0; w < 16; w++) { s_base[w] = r; r += __popcll(s_k64[w]); }
        s_base[16] = r;
    }
    __syncthreads();
    {
        ull kw = s_k64[w_i];
        int kp = (int)((kw >> b_i) & 1ULL);
        ull pmask = (b_i == 63) ? ~0ULL : ((1ULL << (b_i + 1)) - 1ULL);
        int rank = s_base[w_i] + __popcll(kw & pmask);   // inclusive cumsum
        int keep = kp && (rank <= MAX_DET);
        int pv = keep && (sconf[tid] > CONF_MATCH);
        spv[tid] = (unsigned char)pv;
        unsigned bal = __ballot_sync(0xFFFFFFFFu, pv);
        if ((tid & 31) == 0) atomicAdd(&s_npred, __popc(bal));
    }
    __syncthreads();

    // ---- GT matching (one warp per GT) ----
    const int g = tid >> 5;
    const int lane = tid & 31;
    const float4 gb = *(const float4*)(gt_boxes + ((size_t)b * NG + g) * 4);
    const int gc = gt_cls[b * NG + g];
    const float garea = (gb.z - gb.x) * (gb.w - gb.y);

    float best = -1.0f;
    int bidx = 0;
#pragma unroll 4
    for (int t = 0; t < KTOP / 32; t++) {
        int i = t * 32 + lane;
        float v = -1.0f;
        if (spv[i] && scls[i] == gc) {
            float4 p = sbox[i];
            float lx = fmaxf(p.x, gb.x);
            float ly = fmaxf(p.y, gb.y);
            float rx = fminf(p.z, gb.z);
            float ry = fminf(p.w, gb.w);
            float iw = fmaxf(rx - lx, 0.0f);
            float ih = fmaxf(ry - ly, 0.0f);
            float inter = iw * ih;
            float pa = (p.z - p.x) * (p.w - p.y);
            v = inter / (pa + garea - inter + 1e-9f);
        }
        if (v > best) { best = v; bidx = i; }   // ascending i per lane -> first max
    }
    for (int off = 16; off > 0; off >>= 1) {
        float ob = __shfl_down_sync(0xFFFFFFFFu, best, off);
        int   oi = __shfl_down_sync(0xFFFFFFFFu, bidx, off);
        if (ob > best || (ob == best && oi < bidx)) { best = ob; bidx = oi; }
    }
    if (lane == 0) {
        int gm;
        if (s_is_u8) gm = (mb[b * NG + g] != 0);
        else         gm = (((const int*)gt_mask_raw)[b * NG + g] != 0);
        s_biou[g]  = best;
        s_bconf[g] = sconf[bidx];
        int hit = (best > IOU_MATCH) && gm;
        s_hit[g] = hit;
        s_gm[g]  = gm;
        if (gm) {
            atomicAdd(&cat_counts[gc], 1.0f);
            atomicAdd(&sup_counts[cat_to_super[gc]], 1.0f);
        }
    }
    __syncthreads();

    if (tid < 32) {
        int gmv = s_gm[tid], hitv = s_hit[tid];
        float si = hitv ? s_biou[tid]  : 0.0f;
        float sc = hitv ? s_bconf[tid] : 0.0f;
        int n_gt = gmv, n_hit = hitv;
        float sum_iou = si, sum_conf = sc;
        for (int off = 16; off > 0; off >>= 1) {
            n_gt     += __shfl_down_sync(0xFFFFFFFFu, n_gt, off);
            n_hit    += __shfl_down_sync(0xFFFFFFFFu, n_hit, off);
            sum_iou  += __shfl_down_sync(0xFFFFFFFFu, sum_iou, off);
            sum_conf += __shfl_down_sync(0xFFFFFFFFu, sum_conf, off);
        }
        if (tid == 0) {
            float fh = (float)n_hit;
            float mean_iou  = sum_iou / fmaxf(fh, 1.0f);
            float mean_conf = (n_hit > 0) ? (sum_conf / fmaxf(fh, 1.0f)) : 1.0f;
            float correct   = fh / fmaxf((float)n_gt, 1.0f);
            float bc = cat_counts[0]; int mfc = 0;
            for (int c = 1; c < NC; c++)
                if (cat_counts[c] > bc) { bc = cat_counts[c]; mfc = c; }
            float bs = sup_counts[0]; int mfs = 0;
            for (int s = 1; s < NSUP; s++)
                if (sup_counts[s] > bs) { bs = sup_counts[s]; mfs = s; }
            float r0, r1, r2, r3, r4;
            if (n_gt == 0) {
                if (s_npred == 0) { r0 = 1.0f; r1 = 1.0f; r2 = -1.0f; r3 = -1.0f; r4 = 1.0f; }
                else              { r0 = 0.0f; r1 = 1.0f; r2 = -2.0f; r3 = -2.0f; r4 = 0.0f; }
            } else {
                r0 = mean_iou; r1 = mean_conf; r2 = (float)mfc; r3 = (float)mfs; r4 = correct;
            }
            out[b * 5 + 0] = r0;
            out[b * 5 + 1] = r1;
            out[b * 5 + 2] = r2;
            out[b * 5 + 3] = r3;
            out[b * 5 + 4] = r4;
        }
    }
}

// ---------------- launch -----------------------------------------------------------
extern "C" void kernel_launch(void* const* d_in, const int* in_sizes, int n_in,
                              void* d_out, int out_size) {
    const float* preds        = (const float*)d_in[0];
    const float* gt_boxes     = (const float*)d_in[1];
    const int*   gt_cls       = (const int*)d_in[2];
    const void*  gt_mask      = (const void*)d_in[3];
    const int*   cat_to_super = (const int*)d_in[4];
    float* out = (float*)d_out;

    (void)in_sizes; (void)n_in; (void)out_size;

    cudaFuncSetAttribute(k_resolve_match,
                         cudaFuncAttributeMaxDynamicSharedMemorySize,
                         KTOP * 16 * (int)sizeof(ull));

    k_decode<<<(NB * (NA / 4) + 255) / 256, 256>>>(preds);
    k_select<<<NB, 1024, CAP * sizeof(ull)>>>(preds);
    k_nmsmask<<<dim3(36, NB), 256>>>();
    k_resolve_match<<<NB, 1024, KTOP * 16 * sizeof(ull)>>>(gt_boxes, gt_cls, gt_mask,
                                                           cat_to_super, out);
}

// round 14
// speedup vs baseline: 2.3244x; 1.0027x over previous
#include <cuda_runtime.h>
#include <cstdint>

typedef unsigned long long ull;

#define NB 32
#define NA 8400
#define NC 80
#define KTOP 1024
#define NG 32
#define NSUP 16
#define MAX_DET 300
#define CONF_NMS 0.25f
#define IOU_NMS 0.45f
#define CONF_MATCH 0.5f
#define IOU_MATCH 0.6f
#define MAX_WH 7680.0f

// histogram select parameters: bucket = 1 + ((fb - 0x3E800000) >> 11), monotone in conf
#define FB_BASE 0x3E800000u
#define BSHIFT 11
#define NBPAD 9216          // 1024 threads * CH chunks, covers 8193 buckets
#define CH 9
#define CAP 2048            // gather capacity / sort size (expected ~1030)

// ---------------- scratch (global __device__ arrays; no allocation) ----------------
__device__ unsigned               g_hist[NB * NBPAD];   // zero-init; k_select re-zeroes
__device__ __align__(16) float    g_conf[NB * NA];
__device__ __align__(16) int      g_cls[NB * NA];
__device__ float4                 g_box4[NB * KTOP];    // unshifted x1y1x2y2
__device__ float4                 g_sbox4[NB * KTOP];   // class-shifted
__device__ float                  g_area[NB * KTOP];    // area of shifted box
__device__ float                  g_conf_k[NB * KTOP];
__device__ int                    g_cls_k[NB * KTOP];
__device__ __align__(16) ull      g_mask[NB * KTOP * 16];

// upper-triangle 128x128 tile pairs (tr <= tc) over 8 tiles
__device__ const unsigned char c_tr[36] =
    {0,0,0,0,0,0,0,0, 1,1,1,1,1,1,1, 2,2,2,2,2,2, 3,3,3,3,3, 4,4,4,4, 5,5,5, 6,6, 7};
__device__ const unsigned char c_tc[36] =
    {0,1,2,3,4,5,6,7, 1,2,3,4,5,6,7, 2,3,4,5,6,7, 3,4,5,6,7, 4,5,6,7, 5,6,7, 6,7, 7};

__device__ __forceinline__ int conf_bucket(float c) {
    if (c <= 0.0f) return 0;
    unsigned fb = __float_as_uint(c);
    return 1 + (int)((fb - FB_BASE) >> BSHIFT);
}

// ---------------- Kernel 1: decode conf/cls, 4 threads per anchor-group ------------
// sub s scans classes [20s, 20s+20); shfl_xor merge keeps first-max semantics
// (strictly greater wins; tie -> smaller class index).
__global__ void k_decode(const float* __restrict__ preds) {
    int t = blockIdx.x * 256 + threadIdx.x;    // grid exact: 1050*256 == NB*NA
    int grp = t >> 2;
    int sub = t & 3;
    int b = grp / (NA / 4);
    int a4 = (grp - b * (NA / 4)) * 4;
    const float* base = preds + ((size_t)b * 84 + 4 + sub * 20) * NA + a4;

    float4 m = *(const float4*)(base);
    int c0 = sub * 20;
    int ax = c0, ay = c0, az = c0, aw = c0;
#pragma unroll 4
    for (int k = 1; k < 20; k++) {
        float4 v = *(const float4*)(base + (size_t)k * NA);
        int c = c0 + k;
        if (v.x > m.x) { m.x = v.x; ax = c; }   // strict > keeps FIRST max
        if (v.y > m.y) { m.y = v.y; ay = c; }
        if (v.z > m.z) { m.z = v.z; az = c; }
        if (v.w > m.w) { m.w = v.w; aw = c; }
    }
#pragma unroll
    for (int d = 1; d <= 2; d <<= 1) {
        float px = __shfl_xor_sync(0xFFFFFFFFu, m.x, d);
        int   qx = __shfl_xor_sync(0xFFFFFFFFu, ax, d);
        if (px > m.x || (px == m.x && qx < ax)) { m.x = px; ax = qx; }
        float py = __shfl_xor_sync(0xFFFFFFFFu, m.y, d);
        int   qy = __shfl_xor_sync(0xFFFFFFFFu, ay, d);
        if (py > m.y || (py == m.y && qy < ay)) { m.y = py; ay = qy; }
        float pz = __shfl_xor_sync(0xFFFFFFFFu, m.z, d);
        int   qz = __shfl_xor_sync(0xFFFFFFFFu, az, d);
        if (pz > m.z || (pz == m.z && qz < az)) { m.z = pz; az = qz; }
        float pw = __shfl_xor_sync(0xFFFFFFFFu, m.w, d);
        int   qw = __shfl_xor_sync(0xFFFFFFFFu, aw, d);
        if (pw > m.w || (pw == m.w && qw < aw)) { m.w = pw; aw = qw; }
    }
    if (sub == 0) {
        m.x = (m.x > CONF_NMS) ? m.x : 0.0f;
        m.y = (m.y > CONF_NMS) ? m.y : 0.0f;
        m.z = (m.z > CONF_NMS) ? m.z : 0.0f;
        m.w = (m.w > CONF_NMS) ? m.w : 0.0f;
        *(float4*)&g_conf[b * NA + a4] = m;
        *(int4*)&g_cls[b * NA + a4] = make_int4(ax, ay, az, aw);
        unsigned* h = &g_hist[b * NBPAD];
        atomicAdd(&h[conf_bucket(m.x)], 1u);
        atomicAdd(&h[conf_bucket(m.y)], 1u);
        atomicAdd(&h[conf_bucket(m.z)], 1u);
        atomicAdd(&h[conf_bucket(m.w)], 1u);
    }
}

// ---------------- Kernel 2: histogram select + bitonic sort of <=2048 candidates ---
// keys = (~float_bits(conf) << 32) | index : ascending sort == conf desc, idx asc
// (identical ordering to lax.top_k incl. ties)
__global__ __launch_bounds__(1024, 1) void k_select(const float* __restrict__ preds) {
    extern __shared__ ull skey[];               // CAP entries
    __shared__ unsigned s_suf[1024];
    __shared__ unsigned s_wsum[32];
    __shared__ unsigned s_woff[32];
    __shared__ int s_bstar;
    __shared__ int s_cnt;

    const int b = blockIdx.x;
    const int tid = threadIdx.x;
    const int warp = tid >> 5;
    const int lane = tid & 31;
    const int q0 = tid * CH;

    // chunk sums
    unsigned v = 0;
#pragma unroll
    for (int k = 0; k < CH; k++) v += g_hist[b * NBPAD + q0 + k];
    // inclusive suffix scan within warp (lanes ascending = chunks ascending)
    unsigned sv = v;
#pragma unroll
    for (int d = 1; d < 32; d <<= 1) {
        unsigned pv = __shfl_down_sync(0xFFFFFFFFu, sv, d);
        if (lane + d < 32) sv += pv;
    }
    if (lane == 0) s_wsum[warp] = sv;           // lane0 suffix == warp total
    __syncthreads();
    if (warp == 0) {
        unsigned wv = s_wsum[lane];
        unsigned iv = wv;
#pragma unroll
        for (int d = 1; d < 32; d <<= 1) {
            unsigned pv = __shfl_down_sync(0xFFFFFFFFu, iv, d);
            if (lane + d < 32) iv += pv;
        }
        s_woff[lane] = iv - wv;                 // sum over warps > lane
    }
    __syncthreads();
    s_suf[tid] = sv + s_woff[warp];             // inclusive suffix over all chunks
    __syncthreads();

    // unique crossing thread finds threshold bucket B*: largest bucket with
    // count(buckets >= B*) >= KTOP
    unsigned nxt = (tid < 1023) ? s_suf[tid + 1] : 0u;
    if (s_suf[tid] >= KTOP && !(tid < 1023 && nxt >= KTOP)) {
        unsigned running = nxt;
        int B = q0;
        for (int q = q0 + CH - 1; q >= q0; q--) {
            running += g_hist[b * NBPAD + q];
            if (running >= KTOP) { B = q; break; }
        }
        s_bstar = B;
    }
    if (tid == 0) s_cnt = 0;
    for (int i = tid; i < CAP; i += 1024) skey[i] = ~0ULL;   // padding sorts last
    __syncthreads();

    // hist fully consumed -> re-zero for the next graph replay
    for (int i = tid; i < NBPAD; i += 1024) g_hist[b * NBPAD + i] = 0u;

    const int Bs = s_bstar;
    for (int i = tid; i < NA; i += 1024) {
        float c = g_conf[b * NA + i];
        if (conf_bucket(c) >= Bs) {
            int p = atomicAdd(&s_cnt, 1);
            if (p < CAP)
                skey[p] = ((ull)(~__float_as_uint(c)) << 32) | (unsigned)i;
        }
    }
    __syncthreads();

    // bitonic sort of CAP keys
    for (unsigned k = 2; k <= CAP; k <<= 1) {
        for (unsigned j = k >> 1; j > 0; j >>= 1) {
#pragma unroll 1
            for (unsigned i = tid; i < CAP; i += 1024) {
                unsigned ixj = i ^ j;
                if (ixj > i) {
                    ull x = skey[i];
                    ull y = skey[ixj];
                    bool up = ((i & k) == 0);
                    if (up ? (x > y) : (x < y)) { skey[i] = y; skey[ixj] = x; }
                }
            }
            __syncthreads();
        }
    }

    // emit top-KTOP (guaranteed >= KTOP gathered)
    ull key = skey[tid];
    unsigned fb = ~(unsigned)(key >> 32);
    float conf = __uint_as_float(fb);
    int a = (int)(key & 0xFFFFFFFFu);
    const float* base = preds + (size_t)b * 84 * NA;
    float cx = base[a];
    float cy = base[NA + a];
    float w  = base[2 * NA + a];
    float h  = base[3 * NA + a];
    float x1 = cx - w * 0.5f, y1 = cy - h * 0.5f;
    float x2 = cx + w * 0.5f, y2 = cy + h * 0.5f;
    int o = b * KTOP + tid;
    int cls = g_cls[b * NA + a];
    float sh = (float)cls * MAX_WH;
    float sx1 = x1 + sh, sy1 = y1 + sh, sx2 = x2 + sh, sy2 = y2 + sh;
    g_box4[o]  = make_float4(x1, y1, x2, y2);
    g_sbox4[o] = make_float4(sx1, sy1, sx2, sy2);
    g_area[o]  = (sx2 - sx1) * (sy2 - sy1);     // area AFTER shift (bit-matches ref)
    g_conf_k[o] = conf;
    g_cls_k[o]  = cls;
}

// ---------------- Kernel 3: NMS IoU bit-mask, upper triangle only, ballot-based ----
__global__ __launch_bounds__(256) void k_nmsmask() {
    __shared__ float4 srow[128];
    __shared__ float  sarea[128];
    const int b = blockIdx.y;
    const int tr = c_tr[blockIdx.x];
    const int tc = c_tc[blockIdx.x];
    const int tid = threadIdx.x;
    const int lane = tid & 31;
    const int w = tid >> 5;

    if (tid < 128) {
        srow[tid]  = g_sbox4[b * KTOP + tr * 128 + tid];
        sarea[tid] = g_area[b * KTOP + tr * 128 + tid];
    }
    float4 cb[4];
    float  ca[4];
#pragma unroll
    for (int cc = 0; cc < 4; cc++) {
        int j = tc * 128 + cc * 32 + lane;
        cb[cc] = g_sbox4[b * KTOP + j];
        ca[cc] = g_area[b * KTOP + j];
    }
    __syncthreads();

    const bool diag = (tr == tc);
#pragma unroll 4
    for (int rr = 0; rr < 16; rr++) {
        int rl = rr * 8 + w;
        int row = tr * 128 + rl;
        float4 bi = srow[rl];
        float  ai = sarea[rl];
        unsigned bl[4] = {0u, 0u, 0u, 0u};
        bool skip_lo = diag && (rr >= 8);    // rows >= 64 of diag tile: word 2*tc dead
#pragma unroll
        for (int cc = 0; cc < 4; cc++) {
            if (skip_lo && cc < 2) continue;              // warp-uniform skip
            float4 bj = cb[cc];
            float lx = fmaxf(bi.x, bj.x);
            float ly = fmaxf(bi.y, bj.y);
            float rx = fminf(bi.z, bj.z);
            float ry = fminf(bi.w, bj.w);
            float iw = fmaxf(rx - lx, 0.0f);
            float ih = fmaxf(ry - ly, 0.0f);
            float inter = iw * ih;
            float iou = inter / (ai + ca[cc] - inter + 1e-9f);   // same arithmetic
            bl[cc] = __ballot_sync(0xFFFFFFFFu, iou > IOU_NMS);
        }
        ull* mrow = &g_mask[((size_t)b * KTOP + row) * 16];
        if (!skip_lo) {
            if (lane == 0) mrow[2 * tc]     = (ull)bl[0] | ((ull)bl[1] << 32);
            if (lane == 1) mrow[2 * tc + 1] = (ull)bl[2] | ((ull)bl[3] << 32);
        } else {
            if (lane == 1) mrow[2 * tc + 1] = (ull)bl[2] | ((ull)bl[3] << 32);
        }
    }
}

// ---------------- Kernel 4: fixpoint NMS resolve (masks from L2) + GT match --------
// Greedy keep is the UNIQUE fixpoint of
//   F(K)[i] = valid[i] && !exists j<i: K[j] && iou(i,j)>thr.
// Masks are read straight from global (L2-resident, 4 MB); 2 barriers/iter.
__global__ __launch_bounds__(1024, 1) void k_resolve_match(
        const float* __restrict__ gt_boxes,
        const int* __restrict__ gt_cls,
        const void* __restrict__ gt_mask_raw,
        const int* __restrict__ cat_to_super,
        float* __restrict__ out) {
    __shared__ float4 sbox[KTOP];
    __shared__ float  sconf[KTOP];
    __shared__ int    scls[KTOP];
    __shared__ unsigned char spv[KTOP];
    __shared__ unsigned s_bal[32];            // per-warp keep ballots
    __shared__ ull    s_k64[16];              // current keep words
    __shared__ int    s_base[17];
    __shared__ int    s_changed;
    __shared__ float  s_biou[NG];
    __shared__ float  s_bconf[NG];
    __shared__ int    s_hit[NG];
    __shared__ int    s_gm[NG];
    __shared__ float  cat_counts[NC];
    __shared__ float  sup_counts[NSUP];
    __shared__ int    s_npred;
    __shared__ int    s_is_u8;

    const int b = blockIdx.x;
    const int tid = threadIdx.x;
    const int o = b * KTOP + tid;

    float cf = g_conf_k[o];
    sbox[tid]  = g_box4[o];
    sconf[tid] = cf;
    scls[tid]  = g_cls_k[o];
    const bool valid = (cf > 0.0f);
    // initial K0 = valid
    {
        unsigned bal = __ballot_sync(0xFFFFFFFFu, valid);
        if ((tid & 31) == 0) s_bal[tid >> 5] = bal;
    }
    if (tid == 0) { s_npred = 0; s_is_u8 = 0; }
    if (tid < NC)   cat_counts[tid] = 0.0f;
    if (tid < NSUP) sup_counts[tid] = 0.0f;
    // gt_mask dtype probe: int32 0/1 LE => bytes at offset%4!=0 are all zero
    const unsigned char* mb = (const unsigned char*)gt_mask_raw;
    if ((tid & 3) != 0 && mb[tid] != 0) atomicOr(&s_is_u8, 1);
    __syncthreads();
    if (tid < 16)
        s_k64[tid] = (ull)s_bal[2 * tid] | ((ull)s_bal[2 * tid + 1] << 32);
    __syncthreads();

    // ---- fixpoint iteration (2 barriers per iter) ----
    const int w_i = tid >> 6;
    const int b_i = tid & 63;
    const ull selfmask = (1ULL << b_i) - 1ULL;   // bits strictly below i in own word
    const ull* __restrict__ myrow = g_mask + (size_t)o * 16;

    for (;;) {
        ull sup = 0;
#pragma unroll 1
        for (int w = 0; w < w_i; w++) sup |= __ldg(&myrow[w]) & s_k64[w];
        sup |= __ldg(&myrow[w_i]) & s_k64[w_i] & selfmask;
        bool nk = valid && (sup == 0ULL);
        unsigned bal = __ballot_sync(0xFFFFFFFFu, nk);
        if ((tid & 31) == 0) s_bal[tid >> 5] = bal;
        __syncthreads();                 // (A) ballots visible; k64 reads done
        if (tid < 16) {
            ull nw = (ull)s_bal[2 * tid] | ((ull)s_bal[2 * tid + 1] << 32);
            bool ch = (nw != s_k64[tid]);
            s_k64[tid] = nw;
            unsigned cb = __ballot_sync(0x0000FFFFu, ch);
            if (tid == 0) s_changed = (int)cb;
        }
        __syncthreads();                 // (B) k64 + changed visible
        if (!s_changed) break;
    }

    if (tid == 0) {
        int r = 0;
        for (int w = 0; w < 16; w++) { s_base[w] = r; r += __popcll(s_k64[w]); }
        s_base[16] = r;
    }
    __syncthreads();
    {
        ull kw = s_k64[w_i];
        int kp = (int)((kw >> b_i) & 1ULL);
        ull pmask = (b_i == 63) ? ~0ULL : ((1ULL << (b_i + 1)) - 1ULL);
        int rank = s_base[w_i] + __popcll(kw & pmask);   // inclusive cumsum
        int keep = kp && (rank <= MAX_DET);
        int pv = keep && (sconf[tid] > CONF_MATCH);
        spv[tid] = (unsigned char)pv;
        unsigned bal = __ballot_sync(0xFFFFFFFFu, pv);
        if ((tid & 31) == 0) atomicAdd(&s_npred, __popc(bal));
    }
    __syncthreads();

    // ---- GT matching (one warp per GT) ----
    const int g = tid >> 5;
    const int lane = tid & 31;
    const float4 gb = *(const float4*)(gt_boxes + ((size_t)b * NG + g) * 4);
    const int gc = gt_cls[b * NG + g];
    const float garea = (gb.z - gb.x) * (gb.w - gb.y);

    float best = -1.0f;
    int bidx = 0;
#pragma unroll 4
    for (int t = 0; t < KTOP / 32; t++) {
        int i = t * 32 + lane;
        float v = -1.0f;
        if (spv[i] && scls[i] == gc) {
            float4 p = sbox[i];
            float lx = fmaxf(p.x, gb.x);
            float ly = fmaxf(p.y, gb.y);
            float rx = fminf(p.z, gb.z);
            float ry = fminf(p.w, gb.w);
            float iw = fmaxf(rx - lx, 0.0f);
            float ih = fmaxf(ry - ly, 0.0f);
            float inter = iw * ih;
            float pa = (p.z - p.x) * (p.w - p.y);
            v = inter / (pa + garea - inter + 1e-9f);
        }
        if (v > best) { best = v; bidx = i; }   // ascending i per lane -> first max
    }
    for (int off = 16; off > 0; off >>= 1) {
        float ob = __shfl_down_sync(0xFFFFFFFFu, best, off);
        int   oi = __shfl_down_sync(0xFFFFFFFFu, bidx, off);
        if (ob > best || (ob == best && oi < bidx)) { best = ob; bidx = oi; }
    }
    if (lane == 0) {
        int gm;
        if (s_is_u8) gm = (mb[b * NG + g] != 0);
        else         gm = (((const int*)gt_mask_raw)[b * NG + g] != 0);
        s_biou[g]  = best;
        s_bconf[g] = sconf[bidx];
        int hit = (best > IOU_MATCH) && gm;
        s_hit[g] = hit;
        s_gm[g]  = gm;
        if (gm) {
            atomicAdd(&cat_counts[gc], 1.0f);
            atomicAdd(&sup_counts[cat_to_super[gc]], 1.0f);
        }
    }
    __syncthreads();

    if (tid < 32) {
        int gmv = s_gm[tid], hitv = s_hit[tid];
        float si = hitv ? s_biou[tid]  : 0.0f;
        float sc = hitv ? s_bconf[tid] : 0.0f;
        int n_gt = gmv, n_hit = hitv;
        float sum_iou = si, sum_conf = sc;
        for (int off = 16; off > 0; off >>= 1) {
            n_gt     += __shfl_down_sync(0xFFFFFFFFu, n_gt, off);
            n_hit    += __shfl_down_sync(0xFFFFFFFFu, n_hit, off);
            sum_iou  += __shfl_down_sync(0xFFFFFFFFu, sum_iou, off);
            sum_conf += __shfl_down_sync(0xFFFFFFFFu, sum_conf, off);
        }
        if (tid == 0) {
            float fh = (float)n_hit;
            float mean_iou  = sum_iou / fmaxf(fh, 1.0f);
            float mean_conf = (n_hit > 0) ? (sum_conf / fmaxf(fh, 1.0f)) : 1.0f;
            float correct   = fh / fmaxf((float)n_gt, 1.0f);
            float bc = cat_counts[0]; int mfc = 0;
            for (int c = 1; c < NC; c++)
                if (cat_counts[c] > bc) { bc = cat_counts[c]; mfc = c; }
            float bs = sup_counts[0]; int mfs = 0;
            for (int s = 1; s < NSUP; s++)
                if (sup_counts[s] > bs) { bs = sup_counts[s]; mfs = s; }
            float r0, r1, r2, r3, r4;
            if (n_gt == 0) {
                if (s_npred == 0) { r0 = 1.0f; r1 = 1.0f; r2 = -1.0f; r3 = -1.0f; r4 = 1.0f; }
                else              { r0 = 0.0f; r1 = 1.0f; r2 = -2.0f; r3 = -2.0f; r4 = 0.0f; }
            } else {
                r0 = mean_iou; r1 = mean_conf; r2 = (float)mfc; r3 = (float)mfs; r4 = correct;
            }
            out[b * 5 + 0] = r0;
            out[b * 5 + 1] = r1;
            out[b * 5 + 2] = r2;
            out[b * 5 + 3] = r3;
            out[b * 5 + 4] = r4;
        }
    }
}

// ---------------- launch -----------------------------------------------------------
extern "C" void kernel_launch(void* const* d_in, const int* in_sizes, int n_in,
                              void* d_out, int out_size) {
    const float* preds        = (const float*)d_in[0];
    const float* gt_boxes     = (const float*)d_in[1];
    const int*   gt_cls       = (const int*)d_in[2];
    const void*  gt_mask      = (const void*)d_in[3];
    const int*   cat_to_super = (const int*)d_in[4];
    float* out = (float*)d_out;

    (void)in_sizes; (void)n_in; (void)out_size;

    k_decode<<<(NB * NA) / 256, 256>>>(preds);            // exact: 1050 blocks
    k_select<<<NB, 1024, CAP * sizeof(ull)>>>(preds);
    k_nmsmask<<<dim3(36, NB), 256>>>();
    k_resolve_match<<<NB, 1024>>>(gt_boxes, gt_cls, gt_mask, cat_to_super, out);
}

// round 16
// speedup vs baseline: 2.4770x; 1.0657x over previous
#include <cuda_runtime.h>
#include <cstdint>

typedef unsigned long long ull;

#define NB 32
#define NA 8400
#define NC 80
#define KTOP 1024
#define NG 32
#define NSUP 16
#define MAX_DET 300
#define CONF_NMS 0.25f
#define IOU_NMS 0.45f
#define CONF_MATCH 0.5f
#define IOU_MATCH 0.6f
#define MAX_WH 7680.0f

// histogram select parameters: bucket = 1 + ((fb - 0x3E800000) >> 11), monotone in conf
#define FB_BASE 0x3E800000u
#define BSHIFT 11
#define NBPAD 9216          // 1024 threads * CH chunks, covers 8193 buckets
#define CH 9
#define CAP 2048            // gather capacity / sort size (expected ~1100)

// ---------------- scratch (global __device__ arrays; no allocation) ----------------
__device__ unsigned               g_hist[NB * NBPAD];   // zero-init; k_select re-zeroes
__device__ __align__(16) float    g_conf[NB * NA];
__device__ __align__(16) int      g_cls[NB * NA];
__device__ float4                 g_box4[NB * KTOP];    // unshifted x1y1x2y2
__device__ float4                 g_sbox4[NB * KTOP];   // class-shifted
__device__ float                  g_area[NB * KTOP];    // area of shifted box
__device__ float                  g_conf_k[NB * KTOP];
__device__ int                    g_cls_k[NB * KTOP];
__device__ __align__(16) ull      g_mask[NB * KTOP * 16];

// upper-triangle 128x128 tile pairs (tr <= tc) over 8 tiles
__device__ const unsigned char c_tr[36] =
    {0,0,0,0,0,0,0,0, 1,1,1,1,1,1,1, 2,2,2,2,2,2, 3,3,3,3,3, 4,4,4,4, 5,5,5, 6,6, 7};
__device__ const unsigned char c_tc[36] =
    {0,1,2,3,4,5,6,7, 1,2,3,4,5,6,7, 2,3,4,5,6,7, 3,4,5,6,7, 4,5,6,7, 5,6,7, 6,7, 7};

__device__ __forceinline__ int conf_bucket(float c) {
    if (c <= 0.0f) return 0;
    unsigned fb = __float_as_uint(c);
    return 1 + (int)((fb - FB_BASE) >> BSHIFT);
}

// ---------------- Kernel 1: decode conf/cls, 4 threads per anchor-group ------------
// sub s scans classes [20s, 20s+20); shfl_xor merge keeps first-max semantics
// (strictly greater wins; tie -> smaller class index).
__global__ void k_decode(const float* __restrict__ preds) {
    int t = blockIdx.x * 256 + threadIdx.x;    // grid exact: 1050*256 == NB*NA
    int grp = t >> 2;
    int sub = t & 3;
    int b = grp / (NA / 4);
    int a4 = (grp - b * (NA / 4)) * 4;
    const float* base = preds + ((size_t)b * 84 + 4 + sub * 20) * NA + a4;

    float4 m = *(const float4*)(base);
    int c0 = sub * 20;
    int ax = c0, ay = c0, az = c0, aw = c0;
#pragma unroll 4
    for (int k = 1; k < 20; k++) {
        float4 v = *(const float4*)(base + (size_t)k * NA);
        int c = c0 + k;
        if (v.x > m.x) { m.x = v.x; ax = c; }   // strict > keeps FIRST max
        if (v.y > m.y) { m.y = v.y; ay = c; }
        if (v.z > m.z) { m.z = v.z; az = c; }
        if (v.w > m.w) { m.w = v.w; aw = c; }
    }
#pragma unroll
    for (int d = 1; d <= 2; d <<= 1) {
        float px = __shfl_xor_sync(0xFFFFFFFFu, m.x, d);
        int   qx = __shfl_xor_sync(0xFFFFFFFFu, ax, d);
        if (px > m.x || (px == m.x && qx < ax)) { m.x = px; ax = qx; }
        float py = __shfl_xor_sync(0xFFFFFFFFu, m.y, d);
        int   qy = __shfl_xor_sync(0xFFFFFFFFu, ay, d);
        if (py > m.y || (py == m.y && qy < ay)) { m.y = py; ay = qy; }
        float pz = __shfl_xor_sync(0xFFFFFFFFu, m.z, d);
        int   qz = __shfl_xor_sync(0xFFFFFFFFu, az, d);
        if (pz > m.z || (pz == m.z && qz < az)) { m.z = pz; az = qz; }
        float pw = __shfl_xor_sync(0xFFFFFFFFu, m.w, d);
        int   qw = __shfl_xor_sync(0xFFFFFFFFu, aw, d);
        if (pw > m.w || (pw == m.w && qw < aw)) { m.w = pw; aw = qw; }
    }
    if (sub == 0) {
        m.x = (m.x > CONF_NMS) ? m.x : 0.0f;
        m.y = (m.y > CONF_NMS) ? m.y : 0.0f;
        m.z = (m.z > CONF_NMS) ? m.z : 0.0f;
        m.w = (m.w > CONF_NMS) ? m.w : 0.0f;
        *(float4*)&g_conf[b * NA + a4] = m;
        *(int4*)&g_cls[b * NA + a4] = make_int4(ax, ay, az, aw);
        unsigned* h = &g_hist[b * NBPAD];
        atomicAdd(&h[conf_bucket(m.x)], 1u);
        atomicAdd(&h[conf_bucket(m.y)], 1u);
        atomicAdd(&h[conf_bucket(m.z)], 1u);
        atomicAdd(&h[conf_bucket(m.w)], 1u);
    }
}

// ---------------- Kernel 2: histogram select + hybrid bitonic sort -----------------
// keys = (~float_bits(conf) << 32) | index : ascending sort == conf desc, idx asc
// (identical ordering to lax.top_k incl. ties). Sort network identical to classic
// bitonic; stages j>=64 exchange via smem, j<=32 via register shfl, j==1 in-thread.
__global__ __launch_bounds__(1024, 1) void k_select(const float* __restrict__ preds) {
    extern __shared__ ull skey[];               // CAP entries
    __shared__ unsigned s_suf[1024];
    __shared__ unsigned s_wsum[32];
    __shared__ unsigned s_woff[32];
    __shared__ int s_bstar;
    __shared__ int s_cnt;

    const int b = blockIdx.x;
    const int tid = threadIdx.x;
    const int warp = tid >> 5;
    const int lane = tid & 31;
    const int q0 = tid * CH;

    // chunk sums
    unsigned v = 0;
#pragma unroll
    for (int k = 0; k < CH; k++) v += g_hist[b * NBPAD + q0 + k];
    // inclusive suffix scan within warp (lanes ascending = chunks ascending)
    unsigned sv = v;
#pragma unroll
    for (int d = 1; d < 32; d <<= 1) {
        unsigned pv = __shfl_down_sync(0xFFFFFFFFu, sv, d);
        if (lane + d < 32) sv += pv;
    }
    if (lane == 0) s_wsum[warp] = sv;           // lane0 suffix == warp total
    __syncthreads();
    if (warp == 0) {
        unsigned wv = s_wsum[lane];
        unsigned iv = wv;
#pragma unroll
        for (int d = 1; d < 32; d <<= 1) {
            unsigned pv = __shfl_down_sync(0xFFFFFFFFu, iv, d);
            if (lane + d < 32) iv += pv;
        }
        s_woff[lane] = iv - wv;                 // sum over warps > lane
    }
    __syncthreads();
    s_suf[tid] = sv + s_woff[warp];             // inclusive suffix over all chunks
    __syncthreads();

    // unique crossing thread finds threshold bucket B*: largest bucket with
    // count(buckets >= B*) >= KTOP
    unsigned nxt = (tid < 1023) ? s_suf[tid + 1] : 0u;
    if (s_suf[tid] >= KTOP && !(tid < 1023 && nxt >= KTOP)) {
        unsigned running = nxt;
        int B = q0;
        for (int q = q0 + CH - 1; q >= q0; q--) {
            running += g_hist[b * NBPAD + q];
            if (running >= KTOP) { B = q; break; }
        }
        s_bstar = B;
    }
    if (tid == 0) s_cnt = 0;
    for (int i = tid; i < CAP; i += 1024) skey[i] = ~0ULL;   // padding sorts last
    __syncthreads();

    // hist fully consumed -> re-zero for the next graph replay
    for (int i = tid; i < NBPAD; i += 1024) g_hist[b * NBPAD + i] = 0u;

    const int Bs = s_bstar;
    for (int i = tid; i < NA; i += 1024) {
        float c = g_conf[b * NA + i];
        if (conf_bucket(c) >= Bs) {
            int p = atomicAdd(&s_cnt, 1);
            if (p < CAP)
                skey[p] = ((ull)(~__float_as_uint(c)) << 32) | (unsigned)i;
        }
    }
    __syncthreads();

    // ---- hybrid bitonic sort of CAP=2048 keys (2 elements/thread, in registers) ---
    {
        const unsigned t2 = (unsigned)tid * 2u;
        ull e0 = skey[t2], e1 = skey[t2 + 1];
        for (unsigned k = 2; k <= CAP; k <<= 1) {
            // smem stages: j >= 64 (cross-warp exchange)
            for (unsigned j = k >> 1; j >= 64; j >>= 1) {
                skey[t2] = e0; skey[t2 + 1] = e1;
                __syncthreads();
                ull q0 = skey[t2 ^ j];
                ull q1 = skey[(t2 + 1) ^ j];
                bool keepmin = (((t2 & k) == 0u) == ((t2 & j) == 0u));
                e0 = keepmin ? (e0 < q0 ? e0 : q0) : (e0 < q0 ? q0 : e0);
                e1 = keepmin ? (e1 < q1 ? e1 : q1) : (e1 < q1 ? q1 : e1);
                __syncthreads();
            }
            // shfl stages: j = min(k/2,32) .. 2 (partner thread = tid ^ (j/2))
            unsigned jstart = (k >> 1 < 32u) ? (k >> 1) : 32u;
            for (unsigned j = jstart; j >= 2; j >>= 1) {
                ull q0 = __shfl_xor_sync(0xFFFFFFFFu, e0, j >> 1);
                ull q1 = __shfl_xor_sync(0xFFFFFFFFu, e1, j >> 1);
                bool keepmin = (((t2 & k) == 0u) == ((t2 & j) == 0u));
                e0 = keepmin ? (e0 < q0 ? e0 : q0) : (e0 < q0 ? q0 : e0);
                e1 = keepmin ? (e1 < q1 ? e1 : q1) : (e1 < q1 ? q1 : e1);
            }
            // j == 1 stage (in-thread pair: elements t2, t2+1)
            {
                bool up = ((t2 & k) == 0u);
                ull lo = e0 < e1 ? e0 : e1;
                ull hi = e0 < e1 ? e1 : e0;
                e0 = up ? lo : hi;
                e1 = up ? hi : lo;
            }
        }
        skey[t2] = e0; skey[t2 + 1] = e1;
    }
    __syncthreads();

    // emit top-KTOP (guaranteed >= KTOP gathered)
    ull key = skey[tid];
    unsigned fb = ~(unsigned)(key >> 32);
    float conf = __uint_as_float(fb);
    int a = (int)(key & 0xFFFFFFFFu);
    const float* base = preds + (size_t)b * 84 * NA;
    float cx = base[a];
    float cy = base[NA + a];
    float w  = base[2 * NA + a];
    float h  = base[3 * NA + a];
    float x1 = cx - w * 0.5f, y1 = cy - h * 0.5f;
    float x2 = cx + w * 0.5f, y2 = cy + h * 0.5f;
    int o = b * KTOP + tid;
    int cls = g_cls[b * NA + a];
    float sh = (float)cls * MAX_WH;
    float sx1 = x1 + sh, sy1 = y1 + sh, sx2 = x2 + sh, sy2 = y2 + sh;
    g_box4[o]  = make_float4(x1, y1, x2, y2);
    g_sbox4[o] = make_float4(sx1, sy1, sx2, sy2);
    g_area[o]  = (sx2 - sx1) * (sy2 - sy1);     // area AFTER shift (bit-matches ref)
    g_conf_k[o] = conf;
    g_cls_k[o]  = cls;
}

// ---------------- Kernel 3: NMS IoU bit-mask, upper triangle only, ballot-based ----
__global__ __launch_bounds__(256) void k_nmsmask() {
    __shared__ float4 srow[128];
    __shared__ float  sarea[128];
    const int b = blockIdx.y;
    const int tr = c_tr[blockIdx.x];
    const int tc = c_tc[blockIdx.x];
    const int tid = threadIdx.x;
    const int lane = tid & 31;
    const int w = tid >> 5;

    if (tid < 128) {
        srow[tid]  = g_sbox4[b * KTOP + tr * 128 + tid];
        sarea[tid] = g_area[b * KTOP + tr * 128 + tid];
    }
    float4 cb[4];
    float  ca[4];
#pragma unroll
    for (int cc = 0; cc < 4; cc++) {
        int j = tc * 128 + cc * 32 + lane;
        cb[cc] = g_sbox4[b * KTOP + j];
        ca[cc] = g_area[b * KTOP + j];
    }
    __syncthreads();

    const bool diag = (tr == tc);
#pragma unroll 4
    for (int rr = 0; rr < 16; rr++) {
        int rl = rr * 8 + w;
        int row = tr * 128 + rl;
        float4 bi = srow[rl];
        float  ai = sarea[rl];
        unsigned bl[4] = {0u, 0u, 0u, 0u};
        bool skip_lo = diag && (rr >= 8);    // rows >= 64 of diag tile: word 2*tc dead
#pragma unroll
        for (int cc = 0; cc < 4; cc++) {
            if (skip_lo && cc < 2) continue;              // warp-uniform skip
            float4 bj = cb[cc];
            float lx = fmaxf(bi.x, bj.x);
            float ly = fmaxf(bi.y, bj.y);
            float rx = fminf(bi.z, bj.z);
            float ry = fminf(bi.w, bj.w);
            float iw = fmaxf(rx - lx, 0.0f);
            float ih = fmaxf(ry - ly, 0.0f);
            float inter = iw * ih;
            float iou = inter / (ai + ca[cc] - inter + 1e-9f);   // same arithmetic
            bl[cc] = __ballot_sync(0xFFFFFFFFu, iou > IOU_NMS);
        }
        ull* mrow = &g_mask[((size_t)b * KTOP + row) * 16];
        if (!skip_lo) {
            if (lane == 0) mrow[2 * tc]     = (ull)bl[0] | ((ull)bl[1] << 32);
            if (lane == 1) mrow[2 * tc + 1] = (ull)bl[2] | ((ull)bl[3] << 32);
        } else {
            if (lane == 1) mrow[2 * tc + 1] = (ull)bl[2] | ((ull)bl[3] << 32);
        }
    }
}

// ---------------- Kernel 4: fixpoint NMS resolve (masks from L2) + GT match --------
__global__ __launch_bounds__(1024, 1) void k_resolve_match(
        const float* __restrict__ gt_boxes,
        const int* __restrict__ gt_cls,
        const void* __restrict__ gt_mask_raw,
        const int* __restrict__ cat_to_super,
        float* __restrict__ out) {
    __shared__ float4 sbox[KTOP];
    __shared__ float  sconf[KTOP];
    __shared__ int    scls[KTOP];
    __shared__ unsigned char spv[KTOP];
    __shared__ unsigned s_bal[32];            // per-warp keep ballots
    __shared__ ull    s_k64[16];              // current keep words
    __shared__ int    s_base[17];
    __shared__ int    s_changed;
    __shared__ float  s_biou[NG];
    __shared__ float  s_bconf[NG];
    __shared__ int    s_hit[NG];
    __shared__ int    s_gm[NG];
    __shared__ float  cat_counts[NC];
    __shared__ float  sup_counts[NSUP];
    __shared__ int    s_npred;
    __shared__ int    s_is_u8;

    const int b = blockIdx.x;
    const int tid = threadIdx.x;
    const int o = b * KTOP + tid;

    float cf = g_conf_k[o];
    sbox[tid]  = g_box4[o];
    sconf[tid] = cf;
    scls[tid]  = g_cls_k[o];
    const bool valid = (cf > 0.0f);
    // initial K0 = valid
    {
        unsigned bal = __ballot_sync(0xFFFFFFFFu, valid);
        if ((tid & 31) == 0) s_bal[tid >> 5] = bal;
    }
    if (tid == 0) { s_npred = 0; s_is_u8 = 0; }
    if (tid < NC)   cat_counts[tid] = 0.0f;
    if (tid < NSUP) sup_counts[tid] = 0.0f;
    // gt_mask dtype probe: int32 0/1 LE => bytes at offset%4!=0 are all zero
    const unsigned char* mb = (const unsigned char*)gt_mask_raw;
    if ((tid & 3) != 0 && mb[tid] != 0) atomicOr(&s_is_u8, 1);
    __syncthreads();
    if (tid < 16)
        s_k64[tid] = (ull)s_bal[2 * tid] | ((ull)s_bal[2 * tid + 1] << 32);
    __syncthreads();

    // ---- fixpoint iteration (2 barriers per iter) ----
    const int w_i = tid >> 6;
    const int b_i = tid & 63;
    const ull selfmask = (1ULL << b_i) - 1ULL;   // bits strictly below i in own word
    const ull* __restrict__ myrow = g_mask + (size_t)o * 16;

    for (;;) {
        ull sup = 0;
#pragma unroll 1
        for (int w = 0; w < w_i; w++) sup |= __ldg(&myrow[w]) & s_k64[w];
        sup |= __ldg(&myrow[w_i]) & s_k64[w_i] & selfmask;
        bool nk = valid && (sup == 0ULL);
        unsigned bal = __ballot_sync(0xFFFFFFFFu, nk);
        if ((tid & 31) == 0) s_bal[tid >> 5] = bal;
        __syncthreads();                 // (A) ballots visible; k64 reads done
        if (tid < 16) {
            ull nw = (ull)s_bal[2 * tid] | ((ull)s_bal[2 * tid + 1] << 32);
            bool ch = (nw != s_k64[tid]);
            s_k64[tid] = nw;
            unsigned cb = __ballot_sync(0x0000FFFFu, ch);
            if (tid == 0) s_changed = (int)cb;
        }
        __syncthreads();                 // (B) k64 + changed visible
        if (!s_changed) break;
    }

    if (tid == 0) {
        int r = 0;
        for (int w = 0; w < 16; w++) { s_base[w] = r; r += __popcll(s_k64[w]); }
        s_base[16] = r;
    }
    __syncthreads();
    {
        ull kw = s_k64[w_i];
        int kp = (int)((kw >> b_i) & 1ULL);
        ull pmask = (b_i == 63) ? ~0ULL : ((1ULL << (b_i + 1)) - 1ULL);
        int rank = s_base[w_i] + __popcll(kw & pmask);   // inclusive cumsum
        int keep = kp && (rank <= MAX_DET);
        int pv = keep && (sconf[tid] > CONF_MATCH);
        spv[tid] = (unsigned char)pv;
        unsigned bal = __ballot_sync(0xFFFFFFFFu, pv);
        if ((tid & 31) == 0) atomicAdd(&s_npred, __popc(bal));
    }
    __syncthreads();

    // ---- GT matching (one warp per GT) ----
    const int g = tid >> 5;
    const int lane = tid & 31;
    const float4 gb = *(const float4*)(gt_boxes + ((size_t)b * NG + g) * 4);
    const int gc = gt_cls[b * NG + g];
    const float garea = (gb.z - gb.x) * (gb.w - gb.y);

    float best = -1.0f;
    int bidx = 0;
#pragma unroll 4
    for (int t = 0; t < KTOP / 32; t++) {
        int i = t * 32 + lane;
        float v = -1.0f;
        if (spv[i] && scls[i] == gc) {
            float4 p = sbox[i];
            float lx = fmaxf(p.x, gb.x);
            float ly = fmaxf(p.y, gb.y);
            float rx = fminf(p.z, gb.z);
            float ry = fminf(p.w, gb.w);
            float iw = fmaxf(rx - lx, 0.0f);
            float ih = fmaxf(ry - ly, 0.0f);
            float inter = iw * ih;
            float pa = (p.z - p.x) * (p.w - p.y);
            v = inter / (pa + garea - inter + 1e-9f);
        }
        if (v > best) { best = v; bidx = i; }   // ascending i per lane -> first max
    }
    for (int off = 16; off > 0; off >>= 1) {
        float ob = __shfl_down_sync(0xFFFFFFFFu, best, off);
        int   oi = __shfl_down_sync(0xFFFFFFFFu, bidx, off);
        if (ob > best || (ob == best && oi < bidx)) { best = ob; bidx = oi; }
    }
    if (lane == 0) {
        int gm;
        if (s_is_u8) gm = (mb[b * NG + g] != 0);
        else         gm = (((const int*)gt_mask_raw)[b * NG + g] != 0);
        s_biou[g]  = best;
        s_bconf[g] = sconf[bidx];
        int hit = (best > IOU_MATCH) && gm;
        s_hit[g] = hit;
        s_gm[g]  = gm;
        if (gm) {
            atomicAdd(&cat_counts[gc], 1.0f);
            atomicAdd(&sup_counts[cat_to_super[gc]], 1.0f);
        }
    }
    __syncthreads();

    if (tid < 32) {
        int gmv = s_gm[tid], hitv = s_hit[tid];
        float si = hitv ? s_biou[tid]  : 0.0f;
        float sc = hitv ? s_bconf[tid] : 0.0f;
        int n_gt = gmv, n_hit = hitv;
        float sum_iou = si, sum_conf = sc;
        for (int off = 16; off > 0; off >>= 1) {
            n_gt     += __shfl_down_sync(0xFFFFFFFFu, n_gt, off);
            n_hit    += __shfl_down_sync(0xFFFFFFFFu, n_hit, off);
            sum_iou  += __shfl_down_sync(0xFFFFFFFFu, sum_iou, off);
            sum_conf += __shfl_down_sync(0xFFFFFFFFu, sum_conf, off);
        }
        if (tid == 0) {
            float fh = (float)n_hit;
            float mean_iou  = sum_iou / fmaxf(fh, 1.0f);
            float mean_conf = (n_hit > 0) ? (sum_conf / fmaxf(fh, 1.0f)) : 1.0f;
            float correct   = fh / fmaxf((float)n_gt, 1.0f);
            float bc = cat_counts[0]; int mfc = 0;
            for (int c = 1; c < NC; c++)
                if (cat_counts[c] > bc) { bc = cat_counts[c]; mfc = c; }
            float bs = sup_counts[0]; int mfs = 0;
            for (int s = 1; s < NSUP; s++)
                if (sup_counts[s] > bs) { bs = sup_counts[s]; mfs = s; }
            float r0, r1, r2, r3, r4;
            if (n_gt == 0) {
                if (s_npred == 0) { r0 = 1.0f; r1 = 1.0f; r2 = -1.0f; r3 = -1.0f; r4 = 1.0f; }
                else              { r0 = 0.0f; r1 = 1.0f; r2 = -2.0f; r3 = -2.0f; r4 = 0.0f; }
            } else {
                r0 = mean_iou; r1 = mean_conf; r2 = (float)mfc; r3 = (float)mfs; r4 = correct;
            }
            out[b * 5 + 0] = r0;
            out[b * 5 + 1] = r1;
            out[b * 5 + 2] = r2;
            out[b * 5 + 3] = r3;
            out[b * 5 + 4] = r4;
        }
    }
}

// ---------------- launch -----------------------------------------------------------
extern "C" void kernel_launch(void* const* d_in, const int* in_sizes, int n_in,
                              void* d_out, int out_size) {
    const float* preds        = (const float*)d_in[0];
    const float* gt_boxes     = (const float*)d_in[1];
    const int*   gt_cls       = (const int*)d_in[2];
    const void*  gt_mask      = (const void*)d_in[3];
    const int*   cat_to_super = (const int*)d_in[4];
    float* out = (float*)d_out;

    (void)in_sizes; (void)n_in; (void)out_size;

    k_decode<<<(NB * NA) / 256, 256>>>(preds);            // exact: 1050 blocks
    k_select<<<NB, 1024, CAP * sizeof(ull)>>>(preds);
    k_nmsmask<<<dim3(36, NB), 256>>>();
    k_resolve_match<<<NB, 1024>>>(gt_boxes, gt_cls, gt_mask, cat_to_super, out);
}